// round 2
// baseline (speedup 1.0000x reference)
#include <cuda_runtime.h>
#include <math.h>
#include <stdint.h>

// Problem constants (fixed by the reference: B=1, S=4096, D=2048, H=16)
#define S_LEN    4096
#define D_MODEL  2048
#define N_HEADS  16
#define HEAD_DIM 128

// Scratch (allocation-free rule: __device__ globals). 4 x 32MB = 128MB.
__device__ float g_Q[(size_t)S_LEN * D_MODEL];
__device__ float g_K[(size_t)S_LEN * D_MODEL];
__device__ float g_V[(size_t)S_LEN * D_MODEL];
__device__ float g_O[(size_t)S_LEN * D_MODEL];

// ---------------------------------------------------------------------------
// SGEMM: C[M,N] = A[M,K] @ B[K,N], row-major, M%128==0, N%128==0, K%16==0
// 128x128 block tile, BK=16, 256 threads, 8x8 per-thread register tile.
// Software-pipelined: next K-tile is prefetched into registers during compute.
// ---------------------------------------------------------------------------
#define BM 128
#define BN 128
#define BKT 16
#define TM 8
#define TN 8

__device__ __forceinline__ void gemm_body(const float* __restrict__ A,
                                          const float* __restrict__ B,
                                          float* __restrict__ C,
                                          int M, int N, int K)
{
    // +4 pad keeps rows 132 floats = 528B (multiple of 16B) -> float4 reads stay aligned
    __shared__ __align__(16) float As[BKT][BM + 4];
    __shared__ __align__(16) float Bs[BKT][BN + 4];

    const int t  = threadIdx.x;
    const int bn = blockIdx.x;
    const int bm = blockIdx.y;

    const int aRow  = t >> 2;          // 0..63
    const int aK4   = (t & 3) << 2;    // 0,4,8,12
    const int bRow  = t >> 5;          // 0..7
    const int bCol4 = (t & 31) << 2;   // 0..124

    const int cRow = (t >> 4) << 3;    // (t/16)*8
    const int cCol = (t & 15) << 3;    // (t%16)*8

    float acc[TM][TN];
#pragma unroll
    for (int i = 0; i < TM; i++)
#pragma unroll
        for (int j = 0; j < TN; j++) acc[i][j] = 0.0f;

    const float* Aptr = A + (size_t)bm * BM * K;
    const float* Bptr = B + (size_t)bn * BN;

    // Prefetch registers for the software pipeline
    float4 pa0, pa1, pb0, pb1;

    // ---- preload tile kt=0 into registers ----
    pa0 = *reinterpret_cast<const float4*>(Aptr + (size_t)aRow * K + aK4);
    pa1 = *reinterpret_cast<const float4*>(Aptr + (size_t)(aRow + 64) * K + aK4);
    pb0 = *reinterpret_cast<const float4*>(Bptr + (size_t)bRow * N + bCol4);
    pb1 = *reinterpret_cast<const float4*>(Bptr + (size_t)(bRow + 8) * N + bCol4);

    for (int kt = 0; kt < K; kt += BKT) {
        // ---- commit prefetched registers to shared ----
        As[aK4 + 0][aRow]      = pa0.x;
        As[aK4 + 1][aRow]      = pa0.y;
        As[aK4 + 2][aRow]      = pa0.z;
        As[aK4 + 3][aRow]      = pa0.w;
        As[aK4 + 0][aRow + 64] = pa1.x;
        As[aK4 + 1][aRow + 64] = pa1.y;
        As[aK4 + 2][aRow + 64] = pa1.z;
        As[aK4 + 3][aRow + 64] = pa1.w;
        *reinterpret_cast<float4*>(&Bs[bRow][bCol4])     = pb0;
        *reinterpret_cast<float4*>(&Bs[bRow + 8][bCol4]) = pb1;
        __syncthreads();

        // ---- issue prefetch of the NEXT tile (overlaps with compute) ----
        if (kt + BKT < K) {
            const int kn = kt + BKT;
            pa0 = *reinterpret_cast<const float4*>(Aptr + (size_t)aRow * K + kn + aK4);
            pa1 = *reinterpret_cast<const float4*>(Aptr + (size_t)(aRow + 64) * K + kn + aK4);
            pb0 = *reinterpret_cast<const float4*>(Bptr + (size_t)(kn + bRow) * N + bCol4);
            pb1 = *reinterpret_cast<const float4*>(Bptr + (size_t)(kn + bRow + 8) * N + bCol4);
        }

        // ---- compute on the current shared tile ----
#pragma unroll
        for (int kk = 0; kk < BKT; kk++) {
            float ra[TM], rb[TN];
#pragma unroll
            for (int i = 0; i < TM; i += 4)
                *reinterpret_cast<float4*>(&ra[i]) =
                    *reinterpret_cast<const float4*>(&As[kk][cRow + i]);
#pragma unroll
            for (int j = 0; j < TN; j += 4)
                *reinterpret_cast<float4*>(&rb[j]) =
                    *reinterpret_cast<const float4*>(&Bs[kk][cCol + j]);
#pragma unroll
            for (int i = 0; i < TM; i++)
#pragma unroll
                for (int j = 0; j < TN; j++)
                    acc[i][j] += ra[i] * rb[j];
        }
        __syncthreads();
    }

    float* Cptr = C + (size_t)(bm * BM + cRow) * N + (size_t)bn * BN + cCol;
#pragma unroll
    for (int i = 0; i < TM; i++) {
#pragma unroll
        for (int j = 0; j < TN; j += 4) {
            float4 v = make_float4(acc[i][j], acc[i][j + 1], acc[i][j + 2], acc[i][j + 3]);
            *reinterpret_cast<float4*>(Cptr + (size_t)i * N + j) = v;
        }
    }
}

// Fused QKV projections: gridDim.z in {0,1,2} selects weight + destination.
__global__ __launch_bounds__(256, 2)
void mha_qkv_proj(const float* __restrict__ X,
                  const float* __restrict__ Wq,
                  const float* __restrict__ Wk,
                  const float* __restrict__ Wv)
{
    const float* W = (blockIdx.z == 0) ? Wq : (blockIdx.z == 1) ? Wk : Wv;
    float* C = (blockIdx.z == 0) ? g_Q : (blockIdx.z == 1) ? g_K : g_V;
    gemm_body(X, W, C, S_LEN, D_MODEL, D_MODEL);
}

// Output projection: out = O @ Wo
__global__ __launch_bounds__(256, 2)
void mha_out_proj(const float* __restrict__ Wo, float* __restrict__ out)
{
    gemm_body(g_O, Wo, out, S_LEN, D_MODEL, D_MODEL);
}

// ---------------------------------------------------------------------------
// Flash attention (causal, online softmax). One CTA = (64 queries, 1 head).
// 256 threads as a 16x16 grid:
//   scores: 4x4 fragment per thread, S rows r=4*ty+i, cols c=tx+16*j
//   output: 4x8 fragment per thread, O rows r=4*ty+i, cols d=tx+16*j
// ---------------------------------------------------------------------------
#define BQ 64
#define BKV 64
#define QK_PAD (HEAD_DIM + 4)   // 132 floats/row
#define S_PAD  (BKV + 1)        // 65 floats/row

#define ATT_SMEM_FLOATS (3 * BQ * QK_PAD + BQ * S_PAD + 3 * BQ)
#define ATT_SMEM_BYTES  (ATT_SMEM_FLOATS * (int)sizeof(float))

__global__ __launch_bounds__(256, 1)
void mha_flash_attn()
{
    extern __shared__ float sm[];
    float* Qs   = sm;                       // BQ  x QK_PAD (pre-scaled)
    float* Ks   = Qs + BQ * QK_PAD;         // BKV x QK_PAD
    float* Vs   = Ks + BKV * QK_PAD;        // BKV x QK_PAD
    float* Ssh  = Vs + BKV * QK_PAD;        // BQ  x S_PAD
    float* m_sh = Ssh + BQ * S_PAD;
    float* l_sh = m_sh + BQ;
    float* a_sh = l_sh + BQ;

    const int t  = threadIdx.x;
    const int tx = t & 15;
    const int ty = t >> 4;
    const int qb = blockIdx.x;
    const int h  = blockIdx.y;
    const int q0 = qb * BQ;
    const size_t hcol = (size_t)h * HEAD_DIM;

    const float scale = 0.08838834764831845f;  // 1/sqrt(128)

    // Load Q tile (scaled once)
    for (int e = t; e < BQ * HEAD_DIM; e += 256) {
        int r = e >> 7, d = e & 127;
        Qs[r * QK_PAD + d] = g_Q[(size_t)(q0 + r) * D_MODEL + hcol + d] * scale;
    }
    if (t < BQ) { m_sh[t] = -3.0e38f; l_sh[t] = 0.0f; }

    float o[4][8];
#pragma unroll
    for (int i = 0; i < 4; i++)
#pragma unroll
        for (int j = 0; j < 8; j++) o[i][j] = 0.0f;

    for (int jb = 0; jb <= qb; jb++) {
        const int k0 = jb * BKV;

        // Load K,V tiles
        for (int e = t; e < BKV * HEAD_DIM; e += 256) {
            int r = e >> 7, d = e & 127;
            size_t g = (size_t)(k0 + r) * D_MODEL + hcol + d;
            Ks[r * QK_PAD + d] = g_K[g];
            Vs[r * QK_PAD + d] = g_V[g];
        }
        __syncthreads();  // also orders Q-load / m,l init on first iteration

        // S = (Q*scale) K^T
        float acc[4][4];
#pragma unroll
        for (int i = 0; i < 4; i++)
#pragma unroll
            for (int j = 0; j < 4; j++) acc[i][j] = 0.0f;

#pragma unroll 4
        for (int d = 0; d < HEAD_DIM; d++) {
            float qv[4], kv[4];
#pragma unroll
            for (int i = 0; i < 4; i++) qv[i] = Qs[(ty * 4 + i) * QK_PAD + d];
#pragma unroll
            for (int j = 0; j < 4; j++) kv[j] = Ks[(tx + 16 * j) * QK_PAD + d];
#pragma unroll
            for (int i = 0; i < 4; i++)
#pragma unroll
                for (int j = 0; j < 4; j++)
                    acc[i][j] += qv[i] * kv[j];
        }

        const bool diag = (jb == qb);
#pragma unroll
        for (int i = 0; i < 4; i++) {
            int r = ty * 4 + i;
#pragma unroll
            for (int j = 0; j < 4; j++) {
                int c = tx + 16 * j;
                float v = acc[i][j];
                if (diag && c > r) v = -3.0e38f;   // causal mask
                Ssh[r * S_PAD + c] = v;
            }
        }
        __syncthreads();

        // Online softmax: one thread per query row
        if (t < BQ) {
            float m_old = m_sh[t];
            float m = m_old;
            float* Srow = &Ssh[t * S_PAD];
#pragma unroll 8
            for (int c = 0; c < BKV; c++) m = fmaxf(m, Srow[c]);
            float alpha = __expf(m_old - m);
            float s = 0.0f;
#pragma unroll 8
            for (int c = 0; c < BKV; c++) {
                float p = __expf(Srow[c] - m);
                Srow[c] = p;
                s += p;
            }
            m_sh[t] = m;
            l_sh[t] = l_sh[t] * alpha + s;
            a_sh[t] = alpha;
        }
        __syncthreads();

        // O = O*alpha + P @ V
        float al[4];
#pragma unroll
        for (int i = 0; i < 4; i++) al[i] = a_sh[ty * 4 + i];
#pragma unroll
        for (int i = 0; i < 4; i++)
#pragma unroll
            for (int j = 0; j < 8; j++) o[i][j] *= al[i];

#pragma unroll 2
        for (int k = 0; k < BKV; k++) {
            float pv[4], vv[8];
#pragma unroll
            for (int i = 0; i < 4; i++) pv[i] = Ssh[(ty * 4 + i) * S_PAD + k];
#pragma unroll
            for (int j = 0; j < 8; j++) vv[j] = Vs[k * QK_PAD + tx + 16 * j];
#pragma unroll
            for (int i = 0; i < 4; i++)
#pragma unroll
                for (int j = 0; j < 8; j++)
                    o[i][j] += pv[i] * vv[j];
        }
        __syncthreads();  // protect Ssh/Vs before next tile load
    }

    // Normalize and write O
#pragma unroll
    for (int i = 0; i < 4; i++) {
        int r = ty * 4 + i;
        float inv = 1.0f / l_sh[r];
#pragma unroll
        for (int j = 0; j < 8; j++) {
            int d = tx + 16 * j;
            g_O[(size_t)(q0 + r) * D_MODEL + hcol + d] = o[i][j] * inv;
        }
    }
}

// ---------------------------------------------------------------------------
// Launch
// ---------------------------------------------------------------------------
extern "C" void kernel_launch(void* const* d_in, const int* in_sizes, int n_in,
                              void* d_out, int out_size)
{
    const float* X  = (const float*)d_in[0];
    const float* Wq = (const float*)d_in[1];
    const float* Wk = (const float*)d_in[2];
    const float* Wv = (const float*)d_in[3];
    const float* Wo = (const float*)d_in[4];
    float* out = (float*)d_out;

    // 1) Q,K,V projections (fused into one launch via gridDim.z)
    dim3 gproj(D_MODEL / BN, S_LEN / BM, 3);
    mha_qkv_proj<<<gproj, 256>>>(X, Wq, Wk, Wv);

    // 2) Causal flash attention per (query-block, head)
    cudaFuncSetAttribute(mha_flash_attn,
                         cudaFuncAttributeMaxDynamicSharedMemorySize,
                         ATT_SMEM_BYTES);
    dim3 gatt(S_LEN / BQ, N_HEADS);
    mha_flash_attn<<<gatt, 256, ATT_SMEM_BYTES>>>();

    // 3) Output projection
    dim3 gout(D_MODEL / BN, S_LEN / BM);
    mha_out_proj<<<gout, 256>>>(Wo, out);
}

// round 6
// speedup vs baseline: 1.3268x; 1.3268x over previous
#include <cuda_runtime.h>
#include <cuda_bf16.h>
#include <math.h>
#include <stdint.h>

// Problem constants (fixed by the reference: B=1, S=4096, D=2048, H=16)
#define S_LEN    4096
#define D_MODEL  2048
#define KDIM     2048
#define N_HEADS  16
#define HEAD_DIM 128

// ---------------------------------------------------------------------------
// Scratch (__device__ globals; allocation-free rule)
// ---------------------------------------------------------------------------
__device__ float g_Q[(size_t)S_LEN * D_MODEL];
__device__ float g_K[(size_t)S_LEN * D_MODEL];
__device__ float g_V[(size_t)S_LEN * D_MODEL];
__device__ float g_O[(size_t)S_LEN * D_MODEL];

__device__ __nv_bfloat16 g_Xhi[(size_t)S_LEN * D_MODEL];
__device__ __nv_bfloat16 g_Xlo[(size_t)S_LEN * D_MODEL];
__device__ __nv_bfloat16 g_Ohi[(size_t)S_LEN * D_MODEL];
__device__ __nv_bfloat16 g_Olo[(size_t)S_LEN * D_MODEL];
// 4 transposed weights [N,K] (K-major), order: Wq, Wk, Wv, Wo
__device__ __nv_bfloat16 g_Wthi[(size_t)4 * D_MODEL * D_MODEL];
__device__ __nv_bfloat16 g_Wtlo[(size_t)4 * D_MODEL * D_MODEL];

// ---------------------------------------------------------------------------
// Portable helpers (sm_80+): cp.async + mma.sync bf16
// ---------------------------------------------------------------------------
__device__ __forceinline__ uint32_t smem_to_u32(const void* p) {
    uint32_t a;
    asm("{ .reg .u64 t; cvta.to.shared.u64 t, %1; cvt.u32.u64 %0, t; }" : "=r"(a) : "l"(p));
    return a;
}
__device__ __forceinline__ void cp_async16(uint32_t dst, const void* src) {
    asm volatile("cp.async.cg.shared.global [%0], [%1], 16;" :: "r"(dst), "l"(src));
}
#define CP_COMMIT() asm volatile("cp.async.commit_group;" ::: "memory")
#define CP_WAIT1()  asm volatile("cp.async.wait_group 1;" ::: "memory")
#define CP_WAIT0()  asm volatile("cp.async.wait_group 0;" ::: "memory")

// D += A*B, m16n8k16, bf16 inputs, fp32 accumulate
__device__ __forceinline__ void mma_bf16(float* c, const uint32_t* a, const uint32_t* b) {
    asm volatile(
        "mma.sync.aligned.m16n8k16.row.col.f32.bf16.bf16.f32 "
        "{%0,%1,%2,%3}, {%4,%5,%6,%7}, {%8,%9}, {%0,%1,%2,%3};"
        : "+f"(c[0]), "+f"(c[1]), "+f"(c[2]), "+f"(c[3])
        : "r"(a[0]), "r"(a[1]), "r"(a[2]), "r"(a[3]), "r"(b[0]), "r"(b[1]));
}

// ---------------------------------------------------------------------------
// Prep kernels: fp32 -> (hi, lo) bf16 split; weight transpose+split
// ---------------------------------------------------------------------------
__global__ void split_x_kernel(const float* __restrict__ X) {
    size_t i = (size_t)blockIdx.x * blockDim.x + threadIdx.x;
    float v = X[i];
    __nv_bfloat16 h = __float2bfloat16(v);
    g_Xhi[i] = h;
    g_Xlo[i] = __float2bfloat16(v - __bfloat162float(h));
}
__global__ void split_o_kernel() {
    size_t i = (size_t)blockIdx.x * blockDim.x + threadIdx.x;
    float v = g_O[i];
    __nv_bfloat16 h = __float2bfloat16(v);
    g_Ohi[i] = h;
    g_Olo[i] = __float2bfloat16(v - __bfloat162float(h));
}
// W [K,N] fp32 -> Wt_hi/lo [N,K] bf16 (32x32 smem tile transpose)
__global__ void wsplit_t_kernel(const float* __restrict__ Wq, const float* __restrict__ Wk,
                                const float* __restrict__ Wv, const float* __restrict__ Wo) {
    __shared__ float tile[32][33];
    const int w = blockIdx.z;
    const float* W = (w == 0) ? Wq : (w == 1) ? Wk : (w == 2) ? Wv : Wo;
    const size_t off = (size_t)w * D_MODEL * D_MODEL;
    const int n0 = blockIdx.x * 32, k0 = blockIdx.y * 32;
    const int tx = threadIdx.x, ty = threadIdx.y;  // (32, 8)
#pragma unroll
    for (int i = 0; i < 32; i += 8)
        tile[ty + i][tx] = W[(size_t)(k0 + ty + i) * D_MODEL + n0 + tx];
    __syncthreads();
#pragma unroll
    for (int i = 0; i < 32; i += 8) {
        int n = n0 + ty + i, k = k0 + tx;
        float v = tile[tx][ty + i];
        __nv_bfloat16 h = __float2bfloat16(v);
        g_Wthi[off + (size_t)n * KDIM + k] = h;
        g_Wtlo[off + (size_t)n * KDIM + k] = __float2bfloat16(v - __bfloat162float(h));
    }
}

// ---------------------------------------------------------------------------
// bf16x3 tensor-core GEMM via mma.sync:
//   C[4096,2048] fp32 = (Ahi+Alo)[4096,K] x (Bhi+Blo)[2048,K]^T  (B is [N,K])
// Block 128x128xK32, 256 threads (8 warps, 2x4), warp tile 64x32.
// cp.async double-buffered smem; fragments via conflict-free LDS (80B stride).
// ---------------------------------------------------------------------------
#define LDSW 40                       // bf16 elems per smem row (80 B)
#define TILE_B (128 * LDSW * 2)       // 10240 B per operand tile
#define STAGE_B (4 * TILE_B)          // Ahi, Alo, Bhi, Blo
#define GEMM_SMEM (2 * STAGE_B)       // double buffer: 81920 B
#define NSTAGE (KDIM / 32)            // 64

__global__ __launch_bounds__(256, 1)
void gemm_bf16x3(const __nv_bfloat16* __restrict__ Ah, const __nv_bfloat16* __restrict__ Al,
                 const __nv_bfloat16* __restrict__ Bh, const __nv_bfloat16* __restrict__ Bl,
                 float* __restrict__ C)
{
    extern __shared__ char sm_[];
    const int t = threadIdx.x;
    const int lane = t & 31, wid = t >> 5;
    const int wm = wid >> 2, wn = wid & 3;      // 2 x 4 warp grid
    const int bm = blockIdx.y, bn = blockIdx.x;
    const uint32_t sbase = smem_to_u32(sm_);

    float acc[4][4][4];
#pragma unroll
    for (int mi = 0; mi < 4; mi++)
#pragma unroll
        for (int ni = 0; ni < 4; ni++)
#pragma unroll
            for (int e = 0; e < 4; e++) acc[mi][ni][e] = 0.0f;

    const int ldr = t >> 2;       // 0..63 row within half-tile
    const int kc  = t & 3;        // 16B chunk within 64B of k-data

    // per-j constants: tile = j>>1 (0:Ahi 1:Alo 2:Bhi 3:Blo), rowoff = (j&1)*64
    const __nv_bfloat16* srcs[4] = {
        Ah + (size_t)(bm * 128) * KDIM,
        Al + (size_t)(bm * 128) * KDIM,
        Bh + (size_t)(bn * 128) * KDIM,
        Bl + (size_t)(bn * 128) * KDIM };

    // ---- pipeline: load stage 0 ----
    {
        const uint32_t dbase = sbase;  // stage 0 buffer
#pragma unroll
        for (int j = 0; j < 8; j++) {
            const int tile = j >> 1;
            const int row = (j & 1) * 64 + ldr;
            cp_async16(dbase + tile * TILE_B + row * 80 + kc * 16,
                       srcs[tile] + (size_t)row * KDIM + kc * 8);
        }
        CP_COMMIT();
    }

    for (int kt = 0; kt < NSTAGE; kt++) {
        if (kt + 1 < NSTAGE) {
            const int k0 = (kt + 1) * 32;
            const uint32_t dbase = sbase + ((kt + 1) & 1) * STAGE_B;
#pragma unroll
            for (int j = 0; j < 8; j++) {
                const int tile = j >> 1;
                const int row = (j & 1) * 64 + ldr;
                cp_async16(dbase + tile * TILE_B + row * 80 + kc * 16,
                           srcs[tile] + (size_t)row * KDIM + k0 + kc * 8);
            }
            CP_COMMIT();
            CP_WAIT1();
        } else {
            CP_WAIT0();
        }
        __syncthreads();

        const char* st = sm_ + (kt & 1) * STAGE_B;
        const __nv_bfloat16* sAh = (const __nv_bfloat16*)(st);
        const __nv_bfloat16* sAl = (const __nv_bfloat16*)(st + TILE_B);
        const __nv_bfloat16* sBh = (const __nv_bfloat16*)(st + 2 * TILE_B);
        const __nv_bfloat16* sBl = (const __nv_bfloat16*)(st + 3 * TILE_B);

#pragma unroll
        for (int ks = 0; ks < 2; ks++) {
            const int kk = ks * 16 + (lane & 3) * 2;     // k element for this lane
            const int rsub = lane >> 2;                  // 0..7

            uint32_t ah[4][4], al[4][4], bh[4][2], bl[4][2];
#pragma unroll
            for (int mi = 0; mi < 4; mi++) {
                const int r0 = wm * 64 + mi * 16 + rsub;
                const uint32_t* p0h = (const uint32_t*)(sAh + r0 * LDSW + kk);
                const uint32_t* p1h = (const uint32_t*)(sAh + (r0 + 8) * LDSW + kk);
                ah[mi][0] = p0h[0]; ah[mi][1] = p1h[0]; ah[mi][2] = p0h[4]; ah[mi][3] = p1h[4];
                const uint32_t* p0l = (const uint32_t*)(sAl + r0 * LDSW + kk);
                const uint32_t* p1l = (const uint32_t*)(sAl + (r0 + 8) * LDSW + kk);
                al[mi][0] = p0l[0]; al[mi][1] = p1l[0]; al[mi][2] = p0l[4]; al[mi][3] = p1l[4];
            }
#pragma unroll
            for (int ni = 0; ni < 4; ni++) {
                const int rn = wn * 32 + ni * 8 + rsub;
                const uint32_t* pbh = (const uint32_t*)(sBh + rn * LDSW + kk);
                bh[ni][0] = pbh[0]; bh[ni][1] = pbh[4];
                const uint32_t* pbl = (const uint32_t*)(sBl + rn * LDSW + kk);
                bl[ni][0] = pbl[0]; bl[ni][1] = pbl[4];
            }
#pragma unroll
            for (int mi = 0; mi < 4; mi++)
#pragma unroll
                for (int ni = 0; ni < 4; ni++) {
                    mma_bf16(acc[mi][ni], ah[mi], bh[ni]);   // hi*hi
                    mma_bf16(acc[mi][ni], ah[mi], bl[ni]);   // hi*lo
                    mma_bf16(acc[mi][ni], al[mi], bh[ni]);   // lo*hi
                }
        }
        __syncthreads();
    }

    // Epilogue: fragment layout c0,c1 -> (row, col..col+1); c2,c3 -> (row+8, ..)
    float* Cb = C + (size_t)(bm * 128 + wm * 64) * D_MODEL + bn * 128 + wn * 32;
    const int rsub = lane >> 2, csub = (lane & 3) * 2;
#pragma unroll
    for (int mi = 0; mi < 4; mi++)
#pragma unroll
        for (int ni = 0; ni < 4; ni++) {
            const int row = mi * 16 + rsub;
            const int col = ni * 8 + csub;
            *reinterpret_cast<float2*>(Cb + (size_t)row * D_MODEL + col) =
                make_float2(acc[mi][ni][0], acc[mi][ni][1]);
            *reinterpret_cast<float2*>(Cb + (size_t)(row + 8) * D_MODEL + col) =
                make_float2(acc[mi][ni][2], acc[mi][ni][3]);
        }
}

__global__ __launch_bounds__(256, 1)
void qkv_gemm_mma() {
    // forward to gemm body per z via separate launches instead (grid.z used below)
}

// thin wrappers selecting operands (avoid per-thread branching inside hot kernel)
// -- we launch gemm_bf16x3 directly with pointers resolved on host side via
//    device-symbol-free math: use a dispatch kernel approach instead.

// ---------------------------------------------------------------------------
// Flash attention (causal, online softmax) — fp32 path, one CTA = (64 q, 1 head)
// ---------------------------------------------------------------------------
#define BQ 64
#define BKV 64
#define QK_PAD (HEAD_DIM + 4)
#define S_PAD  (BKV + 1)
#define ATT_SMEM_FLOATS (3 * BQ * QK_PAD + BQ * S_PAD + 3 * BQ)
#define ATT_SMEM_BYTES  (ATT_SMEM_FLOATS * (int)sizeof(float))

__global__ __launch_bounds__(256, 1)
void mha_flash_attn()
{
    extern __shared__ float sm[];
    float* Qs   = sm;
    float* Ks   = Qs + BQ * QK_PAD;
    float* Vs   = Ks + BKV * QK_PAD;
    float* Ssh  = Vs + BKV * QK_PAD;
    float* m_sh = Ssh + BQ * S_PAD;
    float* l_sh = m_sh + BQ;
    float* a_sh = l_sh + BQ;

    const int t  = threadIdx.x;
    const int tx = t & 15;
    const int ty = t >> 4;
    const int qb = blockIdx.x;
    const int h  = blockIdx.y;
    const int q0 = qb * BQ;
    const size_t hcol = (size_t)h * HEAD_DIM;

    const float scale = 0.08838834764831845f;  // 1/sqrt(128)

    for (int e = t; e < BQ * HEAD_DIM; e += 256) {
        int r = e >> 7, d = e & 127;
        Qs[r * QK_PAD + d] = g_Q[(size_t)(q0 + r) * D_MODEL + hcol + d] * scale;
    }
    if (t < BQ) { m_sh[t] = -3.0e38f; l_sh[t] = 0.0f; }

    float o[4][8];
#pragma unroll
    for (int i = 0; i < 4; i++)
#pragma unroll
        for (int j = 0; j < 8; j++) o[i][j] = 0.0f;

    for (int jb = 0; jb <= qb; jb++) {
        const int k0 = jb * BKV;
        for (int e = t; e < BKV * HEAD_DIM; e += 256) {
            int r = e >> 7, d = e & 127;
            size_t g = (size_t)(k0 + r) * D_MODEL + hcol + d;
            Ks[r * QK_PAD + d] = g_K[g];
            Vs[r * QK_PAD + d] = g_V[g];
        }
        __syncthreads();

        float acc[4][4];
#pragma unroll
        for (int i = 0; i < 4; i++)
#pragma unroll
            for (int j = 0; j < 4; j++) acc[i][j] = 0.0f;

#pragma unroll 4
        for (int d = 0; d < HEAD_DIM; d++) {
            float qv[4], kv[4];
#pragma unroll
            for (int i = 0; i < 4; i++) qv[i] = Qs[(ty * 4 + i) * QK_PAD + d];
#pragma unroll
            for (int j = 0; j < 4; j++) kv[j] = Ks[(tx + 16 * j) * QK_PAD + d];
#pragma unroll
            for (int i = 0; i < 4; i++)
#pragma unroll
                for (int j = 0; j < 4; j++)
                    acc[i][j] += qv[i] * kv[j];
        }

        const bool diag = (jb == qb);
#pragma unroll
        for (int i = 0; i < 4; i++) {
            int r = ty * 4 + i;
#pragma unroll
            for (int j = 0; j < 4; j++) {
                int c = tx + 16 * j;
                float v = acc[i][j];
                if (diag && c > r) v = -3.0e38f;
                Ssh[r * S_PAD + c] = v;
            }
        }
        __syncthreads();

        if (t < BQ) {
            float m_old = m_sh[t];
            float m = m_old;
            float* Srow = &Ssh[t * S_PAD];
#pragma unroll 8
            for (int c = 0; c < BKV; c++) m = fmaxf(m, Srow[c]);
            float alpha = __expf(m_old - m);
            float s = 0.0f;
#pragma unroll 8
            for (int c = 0; c < BKV; c++) {
                float p = __expf(Srow[c] - m);
                Srow[c] = p;
                s += p;
            }
            m_sh[t] = m;
            l_sh[t] = l_sh[t] * alpha + s;
            a_sh[t] = alpha;
        }
        __syncthreads();

        float al[4];
#pragma unroll
        for (int i = 0; i < 4; i++) al[i] = a_sh[ty * 4 + i];
#pragma unroll
        for (int i = 0; i < 4; i++)
#pragma unroll
            for (int j = 0; j < 8; j++) o[i][j] *= al[i];

#pragma unroll 2
        for (int k = 0; k < BKV; k++) {
            float pv[4], vv[8];
#pragma unroll
            for (int i = 0; i < 4; i++) pv[i] = Ssh[(ty * 4 + i) * S_PAD + k];
#pragma unroll
            for (int j = 0; j < 8; j++) vv[j] = Vs[k * QK_PAD + tx + 16 * j];
#pragma unroll
            for (int i = 0; i < 4; i++)
#pragma unroll
                for (int j = 0; j < 8; j++)
                    o[i][j] += pv[i] * vv[j];
        }
        __syncthreads();
    }

#pragma unroll
    for (int i = 0; i < 4; i++) {
        int r = ty * 4 + i;
        float inv = 1.0f / l_sh[r];
#pragma unroll
        for (int j = 0; j < 8; j++) {
            int d = tx + 16 * j;
            g_O[(size_t)(q0 + r) * D_MODEL + hcol + d] = o[i][j] * inv;
        }
    }
}

// ---------------------------------------------------------------------------
// Device-pointer helper kernels: gemm launched with __device__ arrays needs
// their addresses; take them via small dispatch kernels that call into the
// same grid. Simplest portable way: one wrapper kernel per GEMM that computes
// pointers from the device symbols directly.
// ---------------------------------------------------------------------------
__global__ __launch_bounds__(256, 1)
void qkv_gemm_z(int z, float* dummy) { /* unused */ }

// ---------------------------------------------------------------------------
// Launch
// ---------------------------------------------------------------------------
extern "C" void kernel_launch(void* const* d_in, const int* in_sizes, int n_in,
                              void* d_out, int out_size)
{
    const float* X  = (const float*)d_in[0];
    const float* Wq = (const float*)d_in[1];
    const float* Wk = (const float*)d_in[2];
    const float* Wv = (const float*)d_in[3];
    const float* Wo = (const float*)d_in[4];
    float* out = (float*)d_out;

    cudaFuncSetAttribute(gemm_bf16x3, cudaFuncAttributeMaxDynamicSharedMemorySize, GEMM_SMEM);
    cudaFuncSetAttribute(mha_flash_attn, cudaFuncAttributeMaxDynamicSharedMemorySize, ATT_SMEM_BYTES);

    // resolve device-symbol addresses on host (graph-capture safe; no allocs)
    void *pXhi, *pXlo, *pOhi, *pOlo, *pWthi, *pWtlo, *pQ, *pK, *pV;
    cudaGetSymbolAddress(&pXhi, g_Xhi);
    cudaGetSymbolAddress(&pXlo, g_Xlo);
    cudaGetSymbolAddress(&pOhi, g_Ohi);
    cudaGetSymbolAddress(&pOlo, g_Olo);
    cudaGetSymbolAddress(&pWthi, g_Wthi);
    cudaGetSymbolAddress(&pWtlo, g_Wtlo);
    cudaGetSymbolAddress(&pQ, g_Q);
    cudaGetSymbolAddress(&pK, g_K);
    cudaGetSymbolAddress(&pV, g_V);

    const __nv_bfloat16* Xhi = (const __nv_bfloat16*)pXhi;
    const __nv_bfloat16* Xlo = (const __nv_bfloat16*)pXlo;
    const __nv_bfloat16* Ohi = (const __nv_bfloat16*)pOhi;
    const __nv_bfloat16* Olo = (const __nv_bfloat16*)pOlo;
    const __nv_bfloat16* Wthi = (const __nv_bfloat16*)pWthi;
    const __nv_bfloat16* Wtlo = (const __nv_bfloat16*)pWtlo;
    const size_t wsz = (size_t)D_MODEL * D_MODEL;

    const int nElem = S_LEN * D_MODEL;

    // 1) split X into bf16 hi/lo
    split_x_kernel<<<nElem / 256, 256>>>(X);

    // 2) transpose + split all four weights
    dim3 wb(32, 8), wg(D_MODEL / 32, D_MODEL / 32, 4);
    wsplit_t_kernel<<<wg, wb>>>(Wq, Wk, Wv, Wo);

    // 3) Q,K,V projections on tensor cores (bf16x3 mma.sync)
    dim3 gg(D_MODEL / 128, S_LEN / 128);
    gemm_bf16x3<<<gg, 256, GEMM_SMEM>>>(Xhi, Xlo, Wthi + 0 * wsz, Wtlo + 0 * wsz, (float*)pQ);
    gemm_bf16x3<<<gg, 256, GEMM_SMEM>>>(Xhi, Xlo, Wthi + 1 * wsz, Wtlo + 1 * wsz, (float*)pK);
    gemm_bf16x3<<<gg, 256, GEMM_SMEM>>>(Xhi, Xlo, Wthi + 2 * wsz, Wtlo + 2 * wsz, (float*)pV);

    // 4) causal flash attention (fp32)
    dim3 gatt(S_LEN / BQ, N_HEADS);
    mha_flash_attn<<<gatt, 256, ATT_SMEM_BYTES>>>();

    // 5) split O, then output projection
    split_o_kernel<<<nElem / 256, 256>>>();
    gemm_bf16x3<<<gg, 256, GEMM_SMEM>>>(Ohi, Olo, Wthi + 3 * wsz, Wtlo + 3 * wsz, out);
}

// round 8
// speedup vs baseline: 2.6898x; 2.0273x over previous
#include <cuda_runtime.h>
#include <cuda_bf16.h>
#include <math.h>
#include <stdint.h>

// Problem constants (fixed by the reference: B=1, S=4096, D=2048, H=16)
#define S_LEN    4096
#define D_MODEL  2048
#define KDIM     2048
#define N_HEADS  16
#define HEAD_DIM 128

// ---------------------------------------------------------------------------
// Scratch (__device__ globals; allocation-free rule)
// ---------------------------------------------------------------------------
__device__ float g_Q[(size_t)S_LEN * D_MODEL];
__device__ float g_K[(size_t)S_LEN * D_MODEL];
__device__ float g_V[(size_t)S_LEN * D_MODEL];
__device__ float g_O[(size_t)S_LEN * D_MODEL];

__device__ __nv_bfloat16 g_Xhi[(size_t)S_LEN * D_MODEL];
__device__ __nv_bfloat16 g_Xlo[(size_t)S_LEN * D_MODEL];
__device__ __nv_bfloat16 g_Ohi[(size_t)S_LEN * D_MODEL];
__device__ __nv_bfloat16 g_Olo[(size_t)S_LEN * D_MODEL];
__device__ __nv_bfloat16 g_Wthi[(size_t)4 * D_MODEL * D_MODEL];
__device__ __nv_bfloat16 g_Wtlo[(size_t)4 * D_MODEL * D_MODEL];

// attention operands (bf16 hi/lo). Q pre-scaled by 1/sqrt(hd).
__device__ __nv_bfloat16 g_Qhi[(size_t)S_LEN * D_MODEL];
__device__ __nv_bfloat16 g_Qlo[(size_t)S_LEN * D_MODEL];
__device__ __nv_bfloat16 g_Khi[(size_t)S_LEN * D_MODEL];
__device__ __nv_bfloat16 g_Klo[(size_t)S_LEN * D_MODEL];
// V transposed per head: Vt[c][s] where c = h*128 + d  -> [D_MODEL][S_LEN]
__device__ __nv_bfloat16 g_Vthi[(size_t)D_MODEL * S_LEN];
__device__ __nv_bfloat16 g_Vtlo[(size_t)D_MODEL * S_LEN];

// ---------------------------------------------------------------------------
// Portable helpers (sm_80+): cp.async + mma.sync bf16
// ---------------------------------------------------------------------------
__device__ __forceinline__ uint32_t smem_to_u32(const void* p) {
    uint32_t a;
    asm("{ .reg .u64 t; cvta.to.shared.u64 t, %1; cvt.u32.u64 %0, t; }" : "=r"(a) : "l"(p));
    return a;
}
__device__ __forceinline__ void cp_async16(uint32_t dst, const void* src) {
    asm volatile("cp.async.cg.shared.global [%0], [%1], 16;" :: "r"(dst), "l"(src));
}
#define CP_COMMIT() asm volatile("cp.async.commit_group;" ::: "memory")
#define CP_WAIT1()  asm volatile("cp.async.wait_group 1;" ::: "memory")
#define CP_WAIT0()  asm volatile("cp.async.wait_group 0;" ::: "memory")

__device__ __forceinline__ void mma_bf16(float* c, const uint32_t* a, const uint32_t* b) {
    asm volatile(
        "mma.sync.aligned.m16n8k16.row.col.f32.bf16.bf16.f32 "
        "{%0,%1,%2,%3}, {%4,%5,%6,%7}, {%8,%9}, {%0,%1,%2,%3};"
        : "+f"(c[0]), "+f"(c[1]), "+f"(c[2]), "+f"(c[3])
        : "r"(a[0]), "r"(a[1]), "r"(a[2]), "r"(a[3]), "r"(b[0]), "r"(b[1]));
}
__device__ __forceinline__ uint32_t pack_bf16x2(float lo, float hi) {
    __nv_bfloat162 v = __float22bfloat162_rn(make_float2(lo, hi));
    return *reinterpret_cast<uint32_t*>(&v);
}

// ---------------------------------------------------------------------------
// Prep kernels
// ---------------------------------------------------------------------------
__global__ void split_x_kernel(const float* __restrict__ X) {
    size_t i = (size_t)blockIdx.x * blockDim.x + threadIdx.x;
    float v = X[i];
    __nv_bfloat16 h = __float2bfloat16(v);
    g_Xhi[i] = h;
    g_Xlo[i] = __float2bfloat16(v - __bfloat162float(h));
}
__global__ void split_o_kernel() {
    size_t i = (size_t)blockIdx.x * blockDim.x + threadIdx.x;
    float v = g_O[i];
    __nv_bfloat16 h = __float2bfloat16(v);
    g_Ohi[i] = h;
    g_Olo[i] = __float2bfloat16(v - __bfloat162float(h));
}
__global__ void wsplit_t_kernel(const float* __restrict__ Wq, const float* __restrict__ Wk,
                                const float* __restrict__ Wv, const float* __restrict__ Wo) {
    __shared__ float tile[32][33];
    const int w = blockIdx.z;
    const float* W = (w == 0) ? Wq : (w == 1) ? Wk : (w == 2) ? Wv : Wo;
    const size_t off = (size_t)w * D_MODEL * D_MODEL;
    const int n0 = blockIdx.x * 32, k0 = blockIdx.y * 32;
    const int tx = threadIdx.x, ty = threadIdx.y;  // (32, 8)
#pragma unroll
    for (int i = 0; i < 32; i += 8)
        tile[ty + i][tx] = W[(size_t)(k0 + ty + i) * D_MODEL + n0 + tx];
    __syncthreads();
#pragma unroll
    for (int i = 0; i < 32; i += 8) {
        int n = n0 + ty + i, k = k0 + tx;
        float v = tile[tx][ty + i];
        __nv_bfloat16 h = __float2bfloat16(v);
        g_Wthi[off + (size_t)n * KDIM + k] = h;
        g_Wtlo[off + (size_t)n * KDIM + k] = __float2bfloat16(v - __bfloat162float(h));
    }
}
// Q (scaled) and K: fp32 -> bf16 hi/lo, same layout [S][D]
__global__ void qk_split_kernel() {
    size_t i = (size_t)blockIdx.x * blockDim.x + threadIdx.x;
    const float scale = 0.08838834764831845f;  // 1/sqrt(128)
    float q = g_Q[i] * scale;
    __nv_bfloat16 qh = __float2bfloat16(q);
    g_Qhi[i] = qh;
    g_Qlo[i] = __float2bfloat16(q - __bfloat162float(qh));
    float k = g_K[i];
    __nv_bfloat16 kh = __float2bfloat16(k);
    g_Khi[i] = kh;
    g_Klo[i] = __float2bfloat16(k - __bfloat162float(kh));
}
// V [S][D] fp32 -> Vt hi/lo [D][S] bf16 (coalesced 32x32 transpose)
__global__ void vt_split_kernel() {
    __shared__ float tile[32][33];
    const int s0 = blockIdx.y * 32, c0 = blockIdx.x * 32;
    const int tx = threadIdx.x, ty = threadIdx.y;  // (32, 8)
#pragma unroll
    for (int i = 0; i < 32; i += 8)
        tile[ty + i][tx] = g_V[(size_t)(s0 + ty + i) * D_MODEL + c0 + tx];
    __syncthreads();
#pragma unroll
    for (int i = 0; i < 32; i += 8) {
        int c = c0 + ty + i, s = s0 + tx;
        float v = tile[tx][ty + i];
        __nv_bfloat16 h = __float2bfloat16(v);
        g_Vthi[(size_t)c * S_LEN + s] = h;
        g_Vtlo[(size_t)c * S_LEN + s] = __float2bfloat16(v - __bfloat162float(h));
    }
}

// ---------------------------------------------------------------------------
// bf16x3 tensor-core GEMM (unchanged from R6; measured 365us, tensor=52.6%)
// ---------------------------------------------------------------------------
#define LDSW 40
#define TILE_B (128 * LDSW * 2)
#define STAGE_B (4 * TILE_B)
#define GEMM_SMEM (2 * STAGE_B)
#define NSTAGE (KDIM / 32)

__global__ __launch_bounds__(256, 1)
void gemm_bf16x3(const __nv_bfloat16* __restrict__ Ah, const __nv_bfloat16* __restrict__ Al,
                 const __nv_bfloat16* __restrict__ Bh, const __nv_bfloat16* __restrict__ Bl,
                 float* __restrict__ C)
{
    extern __shared__ char sm_[];
    const int t = threadIdx.x;
    const int lane = t & 31, wid = t >> 5;
    const int wm = wid >> 2, wn = wid & 3;
    const int bm = blockIdx.y, bn = blockIdx.x;
    const uint32_t sbase = smem_to_u32(sm_);

    float acc[4][4][4];
#pragma unroll
    for (int mi = 0; mi < 4; mi++)
#pragma unroll
        for (int ni = 0; ni < 4; ni++)
#pragma unroll
            for (int e = 0; e < 4; e++) acc[mi][ni][e] = 0.0f;

    const int ldr = t >> 2;
    const int kc  = t & 3;

    const __nv_bfloat16* srcs[4] = {
        Ah + (size_t)(bm * 128) * KDIM,
        Al + (size_t)(bm * 128) * KDIM,
        Bh + (size_t)(bn * 128) * KDIM,
        Bl + (size_t)(bn * 128) * KDIM };

    {
        const uint32_t dbase = sbase;
#pragma unroll
        for (int j = 0; j < 8; j++) {
            const int tile = j >> 1;
            const int row = (j & 1) * 64 + ldr;
            cp_async16(dbase + tile * TILE_B + row * 80 + kc * 16,
                       srcs[tile] + (size_t)row * KDIM + kc * 8);
        }
        CP_COMMIT();
    }

    for (int kt = 0; kt < NSTAGE; kt++) {
        if (kt + 1 < NSTAGE) {
            const int k0 = (kt + 1) * 32;
            const uint32_t dbase = sbase + ((kt + 1) & 1) * STAGE_B;
#pragma unroll
            for (int j = 0; j < 8; j++) {
                const int tile = j >> 1;
                const int row = (j & 1) * 64 + ldr;
                cp_async16(dbase + tile * TILE_B + row * 80 + kc * 16,
                           srcs[tile] + (size_t)row * KDIM + k0 + kc * 8);
            }
            CP_COMMIT();
            CP_WAIT1();
        } else {
            CP_WAIT0();
        }
        __syncthreads();

        const char* st = sm_ + (kt & 1) * STAGE_B;
        const __nv_bfloat16* sAh = (const __nv_bfloat16*)(st);
        const __nv_bfloat16* sAl = (const __nv_bfloat16*)(st + TILE_B);
        const __nv_bfloat16* sBh = (const __nv_bfloat16*)(st + 2 * TILE_B);
        const __nv_bfloat16* sBl = (const __nv_bfloat16*)(st + 3 * TILE_B);

#pragma unroll
        for (int ks = 0; ks < 2; ks++) {
            const int kk = ks * 16 + (lane & 3) * 2;
            const int rsub = lane >> 2;

            uint32_t ah[4][4], al[4][4], bh[4][2], bl[4][2];
#pragma unroll
            for (int mi = 0; mi < 4; mi++) {
                const int r0 = wm * 64 + mi * 16 + rsub;
                const uint32_t* p0h = (const uint32_t*)(sAh + r0 * LDSW + kk);
                const uint32_t* p1h = (const uint32_t*)(sAh + (r0 + 8) * LDSW + kk);
                ah[mi][0] = p0h[0]; ah[mi][1] = p1h[0]; ah[mi][2] = p0h[4]; ah[mi][3] = p1h[4];
                const uint32_t* p0l = (const uint32_t*)(sAl + r0 * LDSW + kk);
                const uint32_t* p1l = (const uint32_t*)(sAl + (r0 + 8) * LDSW + kk);
                al[mi][0] = p0l[0]; al[mi][1] = p1l[0]; al[mi][2] = p0l[4]; al[mi][3] = p1l[4];
            }
#pragma unroll
            for (int ni = 0; ni < 4; ni++) {
                const int rn = wn * 32 + ni * 8 + rsub;
                const uint32_t* pbh = (const uint32_t*)(sBh + rn * LDSW + kk);
                bh[ni][0] = pbh[0]; bh[ni][1] = pbh[4];
                const uint32_t* pbl = (const uint32_t*)(sBl + rn * LDSW + kk);
                bl[ni][0] = pbl[0]; bl[ni][1] = pbl[4];
            }
#pragma unroll
            for (int mi = 0; mi < 4; mi++)
#pragma unroll
                for (int ni = 0; ni < 4; ni++) {
                    mma_bf16(acc[mi][ni], ah[mi], bh[ni]);
                    mma_bf16(acc[mi][ni], ah[mi], bl[ni]);
                    mma_bf16(acc[mi][ni], al[mi], bh[ni]);
                }
        }
        __syncthreads();
    }

    float* Cb = C + (size_t)(bm * 128 + wm * 64) * D_MODEL + bn * 128 + wn * 32;
    const int rsub = lane >> 2, csub = (lane & 3) * 2;
#pragma unroll
    for (int mi = 0; mi < 4; mi++)
#pragma unroll
        for (int ni = 0; ni < 4; ni++) {
            const int row = mi * 16 + rsub;
            const int col = ni * 8 + csub;
            *reinterpret_cast<float2*>(Cb + (size_t)row * D_MODEL + col) =
                make_float2(acc[mi][ni][0], acc[mi][ni][1]);
            *reinterpret_cast<float2*>(Cb + (size_t)(row + 8) * D_MODEL + col) =
                make_float2(acc[mi][ni][2], acc[mi][ni][3]);
        }
}

// ---------------------------------------------------------------------------
// FA2-style attention on mma.sync (bf16 split precision).
// CTA = 128 queries x 1 head, 256 threads, 8 warps x 16 query rows.
// KV tiles of 64 keys; online softmax in fp32; P kept in registers.
// ---------------------------------------------------------------------------
#define AQ 128
#define AK 64
#define QSTR 136   // bf16 elems per Q/K smem row (272 B) -> conflict-free
#define VSTR 72    // bf16 elems per Vt smem row (144 B) -> conflict-free

#define SM_QHI 0
#define SM_QLO (SM_QHI + AQ * QSTR * 2)          // 34816
#define SM_KHI (SM_QLO + AQ * QSTR * 2)          // 69632
#define SM_KLO (SM_KHI + AK * QSTR * 2)          // 87040
#define SM_VTHI (SM_KLO + AK * QSTR * 2)         // 104448
#define SM_VTLO (SM_VTHI + HEAD_DIM * VSTR * 2)  // 122880
#define ATT_SMEM (SM_VTLO + HEAD_DIM * VSTR * 2) // 141312

__global__ __launch_bounds__(256, 1)
void mha_fa_mma()
{
    extern __shared__ char sm_[];
    const uint32_t sbase = smem_to_u32(sm_);
    const int t = threadIdx.x;
    const int lane = t & 31, wid = t >> 5;
    const int ib = gridDim.x - 1 - blockIdx.x;   // reversed: long CTAs first
    const int h = blockIdx.y;
    const int q0 = ib * AQ;
    const int rsub = lane >> 2, csub = (lane & 3) * 2;
    const int kk = csub;                          // k-offset base within 16

    const __nv_bfloat16* sQh = (const __nv_bfloat16*)(sm_ + SM_QHI);
    const __nv_bfloat16* sQl = (const __nv_bfloat16*)(sm_ + SM_QLO);
    const __nv_bfloat16* sKh = (const __nv_bfloat16*)(sm_ + SM_KHI);
    const __nv_bfloat16* sKl = (const __nv_bfloat16*)(sm_ + SM_KLO);
    const __nv_bfloat16* sVh = (const __nv_bfloat16*)(sm_ + SM_VTHI);
    const __nv_bfloat16* sVl = (const __nv_bfloat16*)(sm_ + SM_VTLO);

    // ---- load Q tile (once) ----
    {
        const size_t gq = (size_t)q0 * D_MODEL + (size_t)h * HEAD_DIM;
#pragma unroll
        for (int i = 0; i < 8; i++) {
            const int idx = t + i * 256;           // 0..2047
            const int row = idx >> 4, c = idx & 15;
            cp_async16(sbase + SM_QHI + row * (QSTR * 2) + c * 16,
                       g_Qhi + gq + (size_t)row * D_MODEL + c * 8);
            cp_async16(sbase + SM_QLO + row * (QSTR * 2) + c * 16,
                       g_Qlo + gq + (size_t)row * D_MODEL + c * 8);
        }
        CP_COMMIT();
    }

    // accumulators / softmax state
    float accO[16][4];
#pragma unroll
    for (int j = 0; j < 16; j++)
#pragma unroll
        for (int e = 0; e < 4; e++) accO[j][e] = 0.0f;
    float m0 = -1e30f, m1 = -1e30f, l0 = 0.0f, l1 = 0.0f;

    const int nTiles = 2 * ib + 2;
    for (int jb = 0; jb < nTiles; jb++) {
        const int k0 = jb * AK;
        // ---- load K and Vt tiles ----
        {
            const size_t gk = (size_t)k0 * D_MODEL + (size_t)h * HEAD_DIM;
#pragma unroll
            for (int i = 0; i < 4; i++) {
                const int idx = t + i * 256;       // 0..1023
                const int row = idx >> 4, c = idx & 15;
                cp_async16(sbase + SM_KHI + row * (QSTR * 2) + c * 16,
                           g_Khi + gk + (size_t)row * D_MODEL + c * 8);
                cp_async16(sbase + SM_KLO + row * (QSTR * 2) + c * 16,
                           g_Klo + gk + (size_t)row * D_MODEL + c * 8);
            }
            const size_t gv = (size_t)h * HEAD_DIM * S_LEN + k0;
#pragma unroll
            for (int i = 0; i < 4; i++) {
                const int idx = t + i * 256;       // 0..1023
                const int row = idx >> 3, c = idx & 7;
                cp_async16(sbase + SM_VTHI + row * (VSTR * 2) + c * 16,
                           g_Vthi + gv + (size_t)row * S_LEN + c * 8);
                cp_async16(sbase + SM_VTLO + row * (VSTR * 2) + c * 16,
                           g_Vtlo + gv + (size_t)row * S_LEN + c * 8);
            }
            CP_COMMIT();
        }
        CP_WAIT0();
        __syncthreads();

        // ---- S = Q K^T (bf16x3) ----
        float accS[8][4];
#pragma unroll
        for (int j = 0; j < 8; j++)
#pragma unroll
            for (int e = 0; e < 4; e++) accS[j][e] = 0.0f;

#pragma unroll
        for (int ks = 0; ks < 8; ks++) {
            const int kc = ks * 16 + kk;
            uint32_t ah[4], al[4];
            {
                const int r0 = wid * 16 + rsub;
                const uint32_t* p0h = (const uint32_t*)(sQh + r0 * QSTR + kc);
                const uint32_t* p1h = (const uint32_t*)(sQh + (r0 + 8) * QSTR + kc);
                ah[0] = p0h[0]; ah[1] = p1h[0]; ah[2] = p0h[4]; ah[3] = p1h[4];
                const uint32_t* p0l = (const uint32_t*)(sQl + r0 * QSTR + kc);
                const uint32_t* p1l = (const uint32_t*)(sQl + (r0 + 8) * QSTR + kc);
                al[0] = p0l[0]; al[1] = p1l[0]; al[2] = p0l[4]; al[3] = p1l[4];
            }
#pragma unroll
            for (int j = 0; j < 8; j++) {
                const int rn = j * 8 + rsub;
                uint32_t bh[2], bl[2];
                const uint32_t* pbh = (const uint32_t*)(sKh + rn * QSTR + kc);
                bh[0] = pbh[0]; bh[1] = pbh[4];
                const uint32_t* pbl = (const uint32_t*)(sKl + rn * QSTR + kc);
                bl[0] = pbl[0]; bl[1] = pbl[4];
                mma_bf16(accS[j], ah, bh);
                mma_bf16(accS[j], ah, bl);
                mma_bf16(accS[j], al, bh);
            }
        }

        // ---- causal mask (only the two diagonal tiles) ----
        if (jb >= 2 * ib) {
            const int row0 = q0 + wid * 16 + rsub;
            const int row1 = row0 + 8;
#pragma unroll
            for (int j = 0; j < 8; j++) {
                const int c0 = k0 + j * 8 + csub;
                if (c0 > row0)     accS[j][0] = -1e30f;
                if (c0 + 1 > row0) accS[j][1] = -1e30f;
                if (c0 > row1)     accS[j][2] = -1e30f;
                if (c0 + 1 > row1) accS[j][3] = -1e30f;
            }
        }

        // ---- online softmax ----
        float mx0 = -1e30f, mx1 = -1e30f;
#pragma unroll
        for (int j = 0; j < 8; j++) {
            mx0 = fmaxf(mx0, fmaxf(accS[j][0], accS[j][1]));
            mx1 = fmaxf(mx1, fmaxf(accS[j][2], accS[j][3]));
        }
        mx0 = fmaxf(mx0, __shfl_xor_sync(0xffffffffu, mx0, 1));
        mx0 = fmaxf(mx0, __shfl_xor_sync(0xffffffffu, mx0, 2));
        mx1 = fmaxf(mx1, __shfl_xor_sync(0xffffffffu, mx1, 1));
        mx1 = fmaxf(mx1, __shfl_xor_sync(0xffffffffu, mx1, 2));

        const float mn0 = fmaxf(m0, mx0);
        const float mn1 = fmaxf(m1, mx1);
        const float al0 = __expf(m0 - mn0);
        const float al1 = __expf(m1 - mn1);
        m0 = mn0; m1 = mn1;

        float s0 = 0.0f, s1 = 0.0f;
#pragma unroll
        for (int j = 0; j < 8; j++) {
            accS[j][0] = __expf(accS[j][0] - m0);
            accS[j][1] = __expf(accS[j][1] - m0);
            accS[j][2] = __expf(accS[j][2] - m1);
            accS[j][3] = __expf(accS[j][3] - m1);
            s0 += accS[j][0] + accS[j][1];
            s1 += accS[j][2] + accS[j][3];
        }
        s0 += __shfl_xor_sync(0xffffffffu, s0, 1);
        s0 += __shfl_xor_sync(0xffffffffu, s0, 2);
        s1 += __shfl_xor_sync(0xffffffffu, s1, 1);
        s1 += __shfl_xor_sync(0xffffffffu, s1, 2);
        l0 = l0 * al0 + s0;
        l1 = l1 * al1 + s1;

#pragma unroll
        for (int j = 0; j < 16; j++) {
            accO[j][0] *= al0; accO[j][1] *= al0;
            accO[j][2] *= al1; accO[j][3] *= al1;
        }

        // ---- O += P V (bf16x3; P fragments straight from accS) ----
#pragma unroll
        for (int ks = 0; ks < 4; ks++) {
            uint32_t ph[4], pl[4];
            {
                const float* f0 = accS[2 * ks];
                const float* f1 = accS[2 * ks + 1];
                float h00 = __bfloat162float(__float2bfloat16(f0[0]));
                float h01 = __bfloat162float(__float2bfloat16(f0[1]));
                float h02 = __bfloat162float(__float2bfloat16(f0[2]));
                float h03 = __bfloat162float(__float2bfloat16(f0[3]));
                float h10 = __bfloat162float(__float2bfloat16(f1[0]));
                float h11 = __bfloat162float(__float2bfloat16(f1[1]));
                float h12 = __bfloat162float(__float2bfloat16(f1[2]));
                float h13 = __bfloat162float(__float2bfloat16(f1[3]));
                ph[0] = pack_bf16x2(h00, h01);
                ph[1] = pack_bf16x2(h02, h03);
                ph[2] = pack_bf16x2(h10, h11);
                ph[3] = pack_bf16x2(h12, h13);
                pl[0] = pack_bf16x2(f0[0] - h00, f0[1] - h01);
                pl[1] = pack_bf16x2(f0[2] - h02, f0[3] - h03);
                pl[2] = pack_bf16x2(f1[0] - h10, f1[1] - h11);
                pl[3] = pack_bf16x2(f1[2] - h12, f1[3] - h13);
            }
            const int kc = ks * 16 + kk;
#pragma unroll
            for (int j = 0; j < 16; j++) {
                const int rn = j * 8 + rsub;
                uint32_t bvh[2], bvl[2];
                const uint32_t* pvh = (const uint32_t*)(sVh + rn * VSTR + kc);
                bvh[0] = pvh[0]; bvh[1] = pvh[4];
                const uint32_t* pvl = (const uint32_t*)(sVl + rn * VSTR + kc);
                bvl[0] = pvl[0]; bvl[1] = pvl[4];
                mma_bf16(accO[j], ph, bvh);
                mma_bf16(accO[j], ph, bvl);
                mma_bf16(accO[j], pl, bvh);
            }
        }
        __syncthreads();   // smem reads done before next tile overwrites
    }

    // ---- normalize + write O ----
    const float inv0 = 1.0f / l0;
    const float inv1 = 1.0f / l1;
    float* Ob = g_O + (size_t)(q0 + wid * 16 + rsub) * D_MODEL + (size_t)h * HEAD_DIM;
#pragma unroll
    for (int j = 0; j < 16; j++) {
        const int col = j * 8 + csub;
        *reinterpret_cast<float2*>(Ob + col) =
            make_float2(accO[j][0] * inv0, accO[j][1] * inv0);
        *reinterpret_cast<float2*>(Ob + 8 * D_MODEL + col) =
            make_float2(accO[j][2] * inv1, accO[j][3] * inv1);
    }
}

// ---------------------------------------------------------------------------
// Launch
// ---------------------------------------------------------------------------
extern "C" void kernel_launch(void* const* d_in, const int* in_sizes, int n_in,
                              void* d_out, int out_size)
{
    const float* X  = (const float*)d_in[0];
    const float* Wq = (const float*)d_in[1];
    const float* Wk = (const float*)d_in[2];
    const float* Wv = (const float*)d_in[3];
    const float* Wo = (const float*)d_in[4];
    float* out = (float*)d_out;

    cudaFuncSetAttribute(gemm_bf16x3, cudaFuncAttributeMaxDynamicSharedMemorySize, GEMM_SMEM);
    cudaFuncSetAttribute(mha_fa_mma, cudaFuncAttributeMaxDynamicSharedMemorySize, ATT_SMEM);

    void *pXhi, *pXlo, *pOhi, *pOlo, *pWthi, *pWtlo, *pQ, *pK, *pV;
    cudaGetSymbolAddress(&pXhi, g_Xhi);
    cudaGetSymbolAddress(&pXlo, g_Xlo);
    cudaGetSymbolAddress(&pOhi, g_Ohi);
    cudaGetSymbolAddress(&pOlo, g_Olo);
    cudaGetSymbolAddress(&pWthi, g_Wthi);
    cudaGetSymbolAddress(&pWtlo, g_Wtlo);
    cudaGetSymbolAddress(&pQ, g_Q);
    cudaGetSymbolAddress(&pK, g_K);
    cudaGetSymbolAddress(&pV, g_V);

    const __nv_bfloat16* Xhi = (const __nv_bfloat16*)pXhi;
    const __nv_bfloat16* Xlo = (const __nv_bfloat16*)pXlo;
    const __nv_bfloat16* Ohi = (const __nv_bfloat16*)pOhi;
    const __nv_bfloat16* Olo = (const __nv_bfloat16*)pOlo;
    const __nv_bfloat16* Wthi = (const __nv_bfloat16*)pWthi;
    const __nv_bfloat16* Wtlo = (const __nv_bfloat16*)pWtlo;
    const size_t wsz = (size_t)D_MODEL * D_MODEL;

    const int nElem = S_LEN * D_MODEL;

    // 1) split X; transpose+split weights
    split_x_kernel<<<nElem / 256, 256>>>(X);
    dim3 wb(32, 8), wg(D_MODEL / 32, D_MODEL / 32, 4);
    wsplit_t_kernel<<<wg, wb>>>(Wq, Wk, Wv, Wo);

    // 2) Q,K,V projections (tensor cores, bf16x3)
    dim3 gg(D_MODEL / 128, S_LEN / 128);
    gemm_bf16x3<<<gg, 256, GEMM_SMEM>>>(Xhi, Xlo, Wthi + 0 * wsz, Wtlo + 0 * wsz, (float*)pQ);
    gemm_bf16x3<<<gg, 256, GEMM_SMEM>>>(Xhi, Xlo, Wthi + 1 * wsz, Wtlo + 1 * wsz, (float*)pK);
    gemm_bf16x3<<<gg, 256, GEMM_SMEM>>>(Xhi, Xlo, Wthi + 2 * wsz, Wtlo + 2 * wsz, (float*)pV);

    // 3) attention operand prep: Q/K split (+scale), V transpose+split
    qk_split_kernel<<<nElem / 256, 256>>>();
    dim3 vb(32, 8), vg(D_MODEL / 32, S_LEN / 32);
    vt_split_kernel<<<vg, vb>>>();

    // 4) causal flash attention on tensor cores
    dim3 gatt(S_LEN / AQ, N_HEADS);
    mha_fa_mma<<<gatt, 256, ATT_SMEM>>>();

    // 5) split O, output projection
    split_o_kernel<<<nElem / 256, 256>>>();
    gemm_bf16x3<<<gg, 256, GEMM_SMEM>>>(Ohi, Olo, Wthi + 3 * wsz, Wtlo + 3 * wsz, out);
}

// round 9
// speedup vs baseline: 2.8496x; 1.0594x over previous
#include <cuda_runtime.h>
#include <cuda_bf16.h>
#include <math.h>
#include <stdint.h>

// Problem constants (fixed by the reference: B=1, S=4096, D=2048, H=16)
#define S_LEN    4096
#define D_MODEL  2048
#define KDIM     2048
#define N_HEADS  16
#define HEAD_DIM 128

// ---------------------------------------------------------------------------
// Scratch (__device__ globals; allocation-free rule)
// ---------------------------------------------------------------------------
__device__ float g_V[(size_t)S_LEN * D_MODEL];

__device__ __nv_bfloat16 g_Xhi[(size_t)S_LEN * D_MODEL];
__device__ __nv_bfloat16 g_Xlo[(size_t)S_LEN * D_MODEL];
__device__ __nv_bfloat16 g_Ohi[(size_t)S_LEN * D_MODEL];
__device__ __nv_bfloat16 g_Olo[(size_t)S_LEN * D_MODEL];
__device__ __nv_bfloat16 g_Wthi[(size_t)4 * D_MODEL * D_MODEL];
__device__ __nv_bfloat16 g_Wtlo[(size_t)4 * D_MODEL * D_MODEL];

// attention operands (bf16 hi/lo). Q pre-scaled by 1/sqrt(hd).
__device__ __nv_bfloat16 g_Qhi[(size_t)S_LEN * D_MODEL];
__device__ __nv_bfloat16 g_Qlo[(size_t)S_LEN * D_MODEL];
__device__ __nv_bfloat16 g_Khi[(size_t)S_LEN * D_MODEL];
__device__ __nv_bfloat16 g_Klo[(size_t)S_LEN * D_MODEL];
// V transposed per head: Vt[c][s] where c = h*128 + d  -> [D_MODEL][S_LEN]
__device__ __nv_bfloat16 g_Vthi[(size_t)D_MODEL * S_LEN];
__device__ __nv_bfloat16 g_Vtlo[(size_t)D_MODEL * S_LEN];

// ---------------------------------------------------------------------------
// Portable helpers (sm_80+): cp.async + mma.sync bf16
// ---------------------------------------------------------------------------
__device__ __forceinline__ uint32_t smem_to_u32(const void* p) {
    uint32_t a;
    asm("{ .reg .u64 t; cvta.to.shared.u64 t, %1; cvt.u32.u64 %0, t; }" : "=r"(a) : "l"(p));
    return a;
}
__device__ __forceinline__ void cp_async16(uint32_t dst, const void* src) {
    asm volatile("cp.async.cg.shared.global [%0], [%1], 16;" :: "r"(dst), "l"(src));
}
#define CP_COMMIT() asm volatile("cp.async.commit_group;" ::: "memory")
#define CP_WAIT1()  asm volatile("cp.async.wait_group 1;" ::: "memory")
#define CP_WAIT0()  asm volatile("cp.async.wait_group 0;" ::: "memory")

__device__ __forceinline__ void mma_bf16(float* c, const uint32_t* a, const uint32_t* b) {
    asm volatile(
        "mma.sync.aligned.m16n8k16.row.col.f32.bf16.bf16.f32 "
        "{%0,%1,%2,%3}, {%4,%5,%6,%7}, {%8,%9}, {%0,%1,%2,%3};"
        : "+f"(c[0]), "+f"(c[1]), "+f"(c[2]), "+f"(c[3])
        : "r"(a[0]), "r"(a[1]), "r"(a[2]), "r"(a[3]), "r"(b[0]), "r"(b[1]));
}
__device__ __forceinline__ uint32_t pack_bf16x2(float lo, float hi) {
    __nv_bfloat162 v = __float22bfloat162_rn(make_float2(lo, hi));
    return *reinterpret_cast<uint32_t*>(&v);
}

// ---------------------------------------------------------------------------
// Prep kernels
// ---------------------------------------------------------------------------
__global__ void split_x_kernel(const float* __restrict__ X) {
    size_t i = (size_t)blockIdx.x * blockDim.x + threadIdx.x;
    float v = X[i];
    __nv_bfloat16 h = __float2bfloat16(v);
    g_Xhi[i] = h;
    g_Xlo[i] = __float2bfloat16(v - __bfloat162float(h));
}
__global__ void wsplit_t_kernel(const float* __restrict__ Wq, const float* __restrict__ Wk,
                                const float* __restrict__ Wv, const float* __restrict__ Wo) {
    __shared__ float tile[32][33];
    const int w = blockIdx.z;
    const float* W = (w == 0) ? Wq : (w == 1) ? Wk : (w == 2) ? Wv : Wo;
    const size_t off = (size_t)w * D_MODEL * D_MODEL;
    const int n0 = blockIdx.x * 32, k0 = blockIdx.y * 32;
    const int tx = threadIdx.x, ty = threadIdx.y;  // (32, 8)
#pragma unroll
    for (int i = 0; i < 32; i += 8)
        tile[ty + i][tx] = W[(size_t)(k0 + ty + i) * D_MODEL + n0 + tx];
    __syncthreads();
#pragma unroll
    for (int i = 0; i < 32; i += 8) {
        int n = n0 + ty + i, k = k0 + tx;
        float v = tile[tx][ty + i];
        __nv_bfloat16 h = __float2bfloat16(v);
        g_Wthi[off + (size_t)n * KDIM + k] = h;
        g_Wtlo[off + (size_t)n * KDIM + k] = __float2bfloat16(v - __bfloat162float(h));
    }
}
// V [S][D] fp32 -> Vt hi/lo [D][S] bf16 (coalesced 32x32 transpose)
__global__ void vt_split_kernel() {
    __shared__ float tile[32][33];
    const int s0 = blockIdx.y * 32, c0 = blockIdx.x * 32;
    const int tx = threadIdx.x, ty = threadIdx.y;  // (32, 8)
#pragma unroll
    for (int i = 0; i < 32; i += 8)
        tile[ty + i][tx] = g_V[(size_t)(s0 + ty + i) * D_MODEL + c0 + tx];
    __syncthreads();
#pragma unroll
    for (int i = 0; i < 32; i += 8) {
        int c = c0 + ty + i, s = s0 + tx;
        float v = tile[tx][ty + i];
        __nv_bfloat16 h = __float2bfloat16(v);
        g_Vthi[(size_t)c * S_LEN + s] = h;
        g_Vtlo[(size_t)c * S_LEN + s] = __float2bfloat16(v - __bfloat162float(h));
    }
}

// ---------------------------------------------------------------------------
// bf16x3 tensor-core GEMM core (compute accumulators for one 128x128 tile).
// Block 128x128xK32, 256 threads (8 warps 2x4), warp tile 64x32.
// ---------------------------------------------------------------------------
#define LDSW 40
#define TILE_B (128 * LDSW * 2)
#define STAGE_B (4 * TILE_B)
#define GEMM_SMEM (2 * STAGE_B)
#define NSTAGE (KDIM / 32)

__device__ __forceinline__ void gemm_core(const __nv_bfloat16* __restrict__ Ah,
                                          const __nv_bfloat16* __restrict__ Al,
                                          const __nv_bfloat16* __restrict__ Bh,
                                          const __nv_bfloat16* __restrict__ Bl,
                                          char* sm_, float acc[4][4][4])
{
    const int t = threadIdx.x;
    const int lane = t & 31, wid = t >> 5;
    const int wm = wid >> 2, wn = wid & 3;
    const uint32_t sbase = smem_to_u32(sm_);

#pragma unroll
    for (int mi = 0; mi < 4; mi++)
#pragma unroll
        for (int ni = 0; ni < 4; ni++)
#pragma unroll
            for (int e = 0; e < 4; e++) acc[mi][ni][e] = 0.0f;

    const int ldr = t >> 2;
    const int kc  = t & 3;
    const __nv_bfloat16* srcs[4] = { Ah, Al, Bh, Bl };

    {
        const uint32_t dbase = sbase;
#pragma unroll
        for (int j = 0; j < 8; j++) {
            const int tile = j >> 1;
            const int row = (j & 1) * 64 + ldr;
            cp_async16(dbase + tile * TILE_B + row * 80 + kc * 16,
                       srcs[tile] + (size_t)row * KDIM + kc * 8);
        }
        CP_COMMIT();
    }

    for (int kt = 0; kt < NSTAGE; kt++) {
        if (kt + 1 < NSTAGE) {
            const int k0 = (kt + 1) * 32;
            const uint32_t dbase = sbase + ((kt + 1) & 1) * STAGE_B;
#pragma unroll
            for (int j = 0; j < 8; j++) {
                const int tile = j >> 1;
                const int row = (j & 1) * 64 + ldr;
                cp_async16(dbase + tile * TILE_B + row * 80 + kc * 16,
                           srcs[tile] + (size_t)row * KDIM + k0 + kc * 8);
            }
            CP_COMMIT();
            CP_WAIT1();
        } else {
            CP_WAIT0();
        }
        __syncthreads();

        const char* st = sm_ + (kt & 1) * STAGE_B;
        const __nv_bfloat16* sAh = (const __nv_bfloat16*)(st);
        const __nv_bfloat16* sAl = (const __nv_bfloat16*)(st + TILE_B);
        const __nv_bfloat16* sBh = (const __nv_bfloat16*)(st + 2 * TILE_B);
        const __nv_bfloat16* sBl = (const __nv_bfloat16*)(st + 3 * TILE_B);

#pragma unroll
        for (int ks = 0; ks < 2; ks++) {
            const int kk = ks * 16 + (lane & 3) * 2;
            const int rsub = lane >> 2;

            uint32_t ah[4][4], al[4][4], bh[4][2], bl[4][2];
#pragma unroll
            for (int mi = 0; mi < 4; mi++) {
                const int r0 = wm * 64 + mi * 16 + rsub;
                const uint32_t* p0h = (const uint32_t*)(sAh + r0 * LDSW + kk);
                const uint32_t* p1h = (const uint32_t*)(sAh + (r0 + 8) * LDSW + kk);
                ah[mi][0] = p0h[0]; ah[mi][1] = p1h[0]; ah[mi][2] = p0h[4]; ah[mi][3] = p1h[4];
                const uint32_t* p0l = (const uint32_t*)(sAl + r0 * LDSW + kk);
                const uint32_t* p1l = (const uint32_t*)(sAl + (r0 + 8) * LDSW + kk);
                al[mi][0] = p0l[0]; al[mi][1] = p1l[0]; al[mi][2] = p0l[4]; al[mi][3] = p1l[4];
            }
#pragma unroll
            for (int ni = 0; ni < 4; ni++) {
                const int rn = wn * 32 + ni * 8 + rsub;
                const uint32_t* pbh = (const uint32_t*)(sBh + rn * LDSW + kk);
                bh[ni][0] = pbh[0]; bh[ni][1] = pbh[4];
                const uint32_t* pbl = (const uint32_t*)(sBl + rn * LDSW + kk);
                bl[ni][0] = pbl[0]; bl[ni][1] = pbl[4];
            }
#pragma unroll
            for (int mi = 0; mi < 4; mi++)
#pragma unroll
                for (int ni = 0; ni < 4; ni++) {
                    mma_bf16(acc[mi][ni], ah[mi], bh[ni]);
                    mma_bf16(acc[mi][ni], ah[mi], bl[ni]);
                    mma_bf16(acc[mi][ni], al[mi], bh[ni]);
                }
        }
        __syncthreads();
    }
}

// Fused QKV: z=0 -> Q (scaled, bf16 split out), z=1 -> K (split out), z=2 -> V (fp32)
__global__ __launch_bounds__(256, 2)
void qkv_gemm_fused()
{
    extern __shared__ char sm_[];
    const int z = blockIdx.z;
    const int bm = blockIdx.y, bn = blockIdx.x;
    const size_t woff = (size_t)z * D_MODEL * D_MODEL;

    float acc[4][4][4];
    gemm_core(g_Xhi + (size_t)(bm * 128) * KDIM,
              g_Xlo + (size_t)(bm * 128) * KDIM,
              g_Wthi + woff + (size_t)(bn * 128) * KDIM,
              g_Wtlo + woff + (size_t)(bn * 128) * KDIM,
              sm_, acc);

    const int t = threadIdx.x;
    const int lane = t & 31, wid = t >> 5;
    const int wm = wid >> 2, wn = wid & 3;
    const int rsub = lane >> 2, csub = (lane & 3) * 2;
    const int rowB = bm * 128 + wm * 64;
    const int colB = bn * 128 + wn * 32;

    if (z == 2) {
        float* Cb = g_V + (size_t)rowB * D_MODEL + colB;
#pragma unroll
        for (int mi = 0; mi < 4; mi++)
#pragma unroll
            for (int ni = 0; ni < 4; ni++) {
                const int row = mi * 16 + rsub;
                const int col = ni * 8 + csub;
                *reinterpret_cast<float2*>(Cb + (size_t)row * D_MODEL + col) =
                    make_float2(acc[mi][ni][0], acc[mi][ni][1]);
                *reinterpret_cast<float2*>(Cb + (size_t)(row + 8) * D_MODEL + col) =
                    make_float2(acc[mi][ni][2], acc[mi][ni][3]);
            }
    } else {
        const float scale = (z == 0) ? 0.08838834764831845f : 1.0f;
        __nv_bfloat16* Hi = (z == 0) ? g_Qhi : g_Khi;
        __nv_bfloat16* Lo = (z == 0) ? g_Qlo : g_Klo;
#pragma unroll
        for (int mi = 0; mi < 4; mi++)
#pragma unroll
            for (int ni = 0; ni < 4; ni++) {
                const int row = rowB + mi * 16 + rsub;
                const int col = colB + ni * 8 + csub;
#pragma unroll
                for (int half = 0; half < 2; half++) {
                    const int r = row + half * 8;
                    float v0 = acc[mi][ni][2 * half + 0] * scale;
                    float v1 = acc[mi][ni][2 * half + 1] * scale;
                    float h0 = __bfloat162float(__float2bfloat16(v0));
                    float h1 = __bfloat162float(__float2bfloat16(v1));
                    *reinterpret_cast<uint32_t*>(Hi + (size_t)r * D_MODEL + col) =
                        pack_bf16x2(h0, h1);
                    *reinterpret_cast<uint32_t*>(Lo + (size_t)r * D_MODEL + col) =
                        pack_bf16x2(v0 - h0, v1 - h1);
                }
            }
    }
}

// Output projection: fp32 epilogue straight to harness output
__global__ __launch_bounds__(256, 2)
void out_gemm(float* __restrict__ out)
{
    extern __shared__ char sm_[];
    const int bm = blockIdx.y, bn = blockIdx.x;
    const size_t woff = (size_t)3 * D_MODEL * D_MODEL;

    float acc[4][4][4];
    gemm_core(g_Ohi + (size_t)(bm * 128) * KDIM,
              g_Olo + (size_t)(bm * 128) * KDIM,
              g_Wthi + woff + (size_t)(bn * 128) * KDIM,
              g_Wtlo + woff + (size_t)(bn * 128) * KDIM,
              sm_, acc);

    const int t = threadIdx.x;
    const int lane = t & 31, wid = t >> 5;
    const int wm = wid >> 2, wn = wid & 3;
    const int rsub = lane >> 2, csub = (lane & 3) * 2;

    float* Cb = out + (size_t)(bm * 128 + wm * 64) * D_MODEL + bn * 128 + wn * 32;
#pragma unroll
    for (int mi = 0; mi < 4; mi++)
#pragma unroll
        for (int ni = 0; ni < 4; ni++) {
            const int row = mi * 16 + rsub;
            const int col = ni * 8 + csub;
            *reinterpret_cast<float2*>(Cb + (size_t)row * D_MODEL + col) =
                make_float2(acc[mi][ni][0], acc[mi][ni][1]);
            *reinterpret_cast<float2*>(Cb + (size_t)(row + 8) * D_MODEL + col) =
                make_float2(acc[mi][ni][2], acc[mi][ni][3]);
        }
}

// ---------------------------------------------------------------------------
// FA2-style attention on mma.sync (bf16 split precision).
// CTA = 128 queries x 1 head, 256 threads, 8 warps x 16 query rows.
// KV tiles of 64 keys; online softmax in fp32; P kept in registers.
// Epilogue writes O directly as bf16 hi/lo splits.
// ---------------------------------------------------------------------------
#define AQ 128
#define AK 64
#define QSTR 136   // bf16 elems per Q/K smem row (272 B) -> conflict-free
#define VSTR 72    // bf16 elems per Vt smem row (144 B) -> conflict-free

#define SM_QHI 0
#define SM_QLO (SM_QHI + AQ * QSTR * 2)
#define SM_KHI (SM_QLO + AQ * QSTR * 2)
#define SM_KLO (SM_KHI + AK * QSTR * 2)
#define SM_VTHI (SM_KLO + AK * QSTR * 2)
#define SM_VTLO (SM_VTHI + HEAD_DIM * VSTR * 2)
#define ATT_SMEM (SM_VTLO + HEAD_DIM * VSTR * 2)

__global__ __launch_bounds__(256, 1)
void mha_fa_mma()
{
    extern __shared__ char sm_[];
    const uint32_t sbase = smem_to_u32(sm_);
    const int t = threadIdx.x;
    const int lane = t & 31, wid = t >> 5;
    const int ib = gridDim.x - 1 - blockIdx.x;   // reversed: long CTAs first
    const int h = blockIdx.y;
    const int q0 = ib * AQ;
    const int rsub = lane >> 2, csub = (lane & 3) * 2;
    const int kk = csub;

    const __nv_bfloat16* sQh = (const __nv_bfloat16*)(sm_ + SM_QHI);
    const __nv_bfloat16* sQl = (const __nv_bfloat16*)(sm_ + SM_QLO);
    const __nv_bfloat16* sKh = (const __nv_bfloat16*)(sm_ + SM_KHI);
    const __nv_bfloat16* sKl = (const __nv_bfloat16*)(sm_ + SM_KLO);
    const __nv_bfloat16* sVh = (const __nv_bfloat16*)(sm_ + SM_VTHI);
    const __nv_bfloat16* sVl = (const __nv_bfloat16*)(sm_ + SM_VTLO);

    // ---- load Q tile (once) ----
    {
        const size_t gq = (size_t)q0 * D_MODEL + (size_t)h * HEAD_DIM;
#pragma unroll
        for (int i = 0; i < 8; i++) {
            const int idx = t + i * 256;
            const int row = idx >> 4, c = idx & 15;
            cp_async16(sbase + SM_QHI + row * (QSTR * 2) + c * 16,
                       g_Qhi + gq + (size_t)row * D_MODEL + c * 8);
            cp_async16(sbase + SM_QLO + row * (QSTR * 2) + c * 16,
                       g_Qlo + gq + (size_t)row * D_MODEL + c * 8);
        }
        CP_COMMIT();
    }

    float accO[16][4];
#pragma unroll
    for (int j = 0; j < 16; j++)
#pragma unroll
        for (int e = 0; e < 4; e++) accO[j][e] = 0.0f;
    float m0 = -1e30f, m1 = -1e30f, l0 = 0.0f, l1 = 0.0f;

    const int nTiles = 2 * ib + 2;
    for (int jb = 0; jb < nTiles; jb++) {
        const int k0 = jb * AK;
        {
            const size_t gk = (size_t)k0 * D_MODEL + (size_t)h * HEAD_DIM;
#pragma unroll
            for (int i = 0; i < 4; i++) {
                const int idx = t + i * 256;
                const int row = idx >> 4, c = idx & 15;
                cp_async16(sbase + SM_KHI + row * (QSTR * 2) + c * 16,
                           g_Khi + gk + (size_t)row * D_MODEL + c * 8);
                cp_async16(sbase + SM_KLO + row * (QSTR * 2) + c * 16,
                           g_Klo + gk + (size_t)row * D_MODEL + c * 8);
            }
            const size_t gv = (size_t)h * HEAD_DIM * S_LEN + k0;
#pragma unroll
            for (int i = 0; i < 4; i++) {
                const int idx = t + i * 256;
                const int row = idx >> 3, c = idx & 7;
                cp_async16(sbase + SM_VTHI + row * (VSTR * 2) + c * 16,
                           g_Vthi + gv + (size_t)row * S_LEN + c * 8);
                cp_async16(sbase + SM_VTLO + row * (VSTR * 2) + c * 16,
                           g_Vtlo + gv + (size_t)row * S_LEN + c * 8);
            }
            CP_COMMIT();
        }
        CP_WAIT0();
        __syncthreads();

        // ---- S = Q K^T (bf16x3) ----
        float accS[8][4];
#pragma unroll
        for (int j = 0; j < 8; j++)
#pragma unroll
            for (int e = 0; e < 4; e++) accS[j][e] = 0.0f;

#pragma unroll
        for (int ks = 0; ks < 8; ks++) {
            const int kc = ks * 16 + kk;
            uint32_t ah[4], al[4];
            {
                const int r0 = wid * 16 + rsub;
                const uint32_t* p0h = (const uint32_t*)(sQh + r0 * QSTR + kc);
                const uint32_t* p1h = (const uint32_t*)(sQh + (r0 + 8) * QSTR + kc);
                ah[0] = p0h[0]; ah[1] = p1h[0]; ah[2] = p0h[4]; ah[3] = p1h[4];
                const uint32_t* p0l = (const uint32_t*)(sQl + r0 * QSTR + kc);
                const uint32_t* p1l = (const uint32_t*)(sQl + (r0 + 8) * QSTR + kc);
                al[0] = p0l[0]; al[1] = p1l[0]; al[2] = p0l[4]; al[3] = p1l[4];
            }
#pragma unroll
            for (int j = 0; j < 8; j++) {
                const int rn = j * 8 + rsub;
                uint32_t bh[2], bl[2];
                const uint32_t* pbh = (const uint32_t*)(sKh + rn * QSTR + kc);
                bh[0] = pbh[0]; bh[1] = pbh[4];
                const uint32_t* pbl = (const uint32_t*)(sKl + rn * QSTR + kc);
                bl[0] = pbl[0]; bl[1] = pbl[4];
                mma_bf16(accS[j], ah, bh);
                mma_bf16(accS[j], ah, bl);
                mma_bf16(accS[j], al, bh);
            }
        }

        // ---- causal mask (only the two diagonal tiles) ----
        if (jb >= 2 * ib) {
            const int row0 = q0 + wid * 16 + rsub;
            const int row1 = row0 + 8;
#pragma unroll
            for (int j = 0; j < 8; j++) {
                const int c0 = k0 + j * 8 + csub;
                if (c0 > row0)     accS[j][0] = -1e30f;
                if (c0 + 1 > row0) accS[j][1] = -1e30f;
                if (c0 > row1)     accS[j][2] = -1e30f;
                if (c0 + 1 > row1) accS[j][3] = -1e30f;
            }
        }

        // ---- online softmax ----
        float mx0 = -1e30f, mx1 = -1e30f;
#pragma unroll
        for (int j = 0; j < 8; j++) {
            mx0 = fmaxf(mx0, fmaxf(accS[j][0], accS[j][1]));
            mx1 = fmaxf(mx1, fmaxf(accS[j][2], accS[j][3]));
        }
        mx0 = fmaxf(mx0, __shfl_xor_sync(0xffffffffu, mx0, 1));
        mx0 = fmaxf(mx0, __shfl_xor_sync(0xffffffffu, mx0, 2));
        mx1 = fmaxf(mx1, __shfl_xor_sync(0xffffffffu, mx1, 1));
        mx1 = fmaxf(mx1, __shfl_xor_sync(0xffffffffu, mx1, 2));

        const float mn0 = fmaxf(m0, mx0);
        const float mn1 = fmaxf(m1, mx1);
        const float al0 = __expf(m0 - mn0);
        const float al1 = __expf(m1 - mn1);
        m0 = mn0; m1 = mn1;

        float s0 = 0.0f, s1 = 0.0f;
#pragma unroll
        for (int j = 0; j < 8; j++) {
            accS[j][0] = __expf(accS[j][0] - m0);
            accS[j][1] = __expf(accS[j][1] - m0);
            accS[j][2] = __expf(accS[j][2] - m1);
            accS[j][3] = __expf(accS[j][3] - m1);
            s0 += accS[j][0] + accS[j][1];
            s1 += accS[j][2] + accS[j][3];
        }
        s0 += __shfl_xor_sync(0xffffffffu, s0, 1);
        s0 += __shfl_xor_sync(0xffffffffu, s0, 2);
        s1 += __shfl_xor_sync(0xffffffffu, s1, 1);
        s1 += __shfl_xor_sync(0xffffffffu, s1, 2);
        l0 = l0 * al0 + s0;
        l1 = l1 * al1 + s1;

#pragma unroll
        for (int j = 0; j < 16; j++) {
            accO[j][0] *= al0; accO[j][1] *= al0;
            accO[j][2] *= al1; accO[j][3] *= al1;
        }

        // ---- O += P V (bf16x3; P fragments straight from accS) ----
#pragma unroll
        for (int ks = 0; ks < 4; ks++) {
            uint32_t ph[4], pl[4];
            {
                const float* f0 = accS[2 * ks];
                const float* f1 = accS[2 * ks + 1];
                float h00 = __bfloat162float(__float2bfloat16(f0[0]));
                float h01 = __bfloat162float(__float2bfloat16(f0[1]));
                float h02 = __bfloat162float(__float2bfloat16(f0[2]));
                float h03 = __bfloat162float(__float2bfloat16(f0[3]));
                float h10 = __bfloat162float(__float2bfloat16(f1[0]));
                float h11 = __bfloat162float(__float2bfloat16(f1[1]));
                float h12 = __bfloat162float(__float2bfloat16(f1[2]));
                float h13 = __bfloat162float(__float2bfloat16(f1[3]));
                ph[0] = pack_bf16x2(h00, h01);
                ph[1] = pack_bf16x2(h02, h03);
                ph[2] = pack_bf16x2(h10, h11);
                ph[3] = pack_bf16x2(h12, h13);
                pl[0] = pack_bf16x2(f0[0] - h00, f0[1] - h01);
                pl[1] = pack_bf16x2(f0[2] - h02, f0[3] - h03);
                pl[2] = pack_bf16x2(f1[0] - h10, f1[1] - h11);
                pl[3] = pack_bf16x2(f1[2] - h12, f1[3] - h13);
            }
            const int kc = ks * 16 + kk;
#pragma unroll
            for (int j = 0; j < 16; j++) {
                const int rn = j * 8 + rsub;
                uint32_t bvh[2], bvl[2];
                const uint32_t* pvh = (const uint32_t*)(sVh + rn * VSTR + kc);
                bvh[0] = pvh[0]; bvh[1] = pvh[4];
                const uint32_t* pvl = (const uint32_t*)(sVl + rn * VSTR + kc);
                bvl[0] = pvl[0]; bvl[1] = pvl[4];
                mma_bf16(accO[j], ph, bvh);
                mma_bf16(accO[j], ph, bvl);
                mma_bf16(accO[j], pl, bvh);
            }
        }
        __syncthreads();
    }

    // ---- normalize + write O directly as bf16 hi/lo splits ----
    const float inv0 = 1.0f / l0;
    const float inv1 = 1.0f / l1;
    const size_t obase = (size_t)(q0 + wid * 16 + rsub) * D_MODEL + (size_t)h * HEAD_DIM;
#pragma unroll
    for (int j = 0; j < 16; j++) {
        const int col = j * 8 + csub;
#pragma unroll
        for (int half = 0; half < 2; half++) {
            const size_t off = obase + (size_t)(half * 8) * D_MODEL + col;
            float v0 = accO[j][2 * half + 0] * (half ? inv1 : inv0);
            float v1 = accO[j][2 * half + 1] * (half ? inv1 : inv0);
            float h0 = __bfloat162float(__float2bfloat16(v0));
            float h1 = __bfloat162float(__float2bfloat16(v1));
            *reinterpret_cast<uint32_t*>(g_Ohi + off) = pack_bf16x2(h0, h1);
            *reinterpret_cast<uint32_t*>(g_Olo + off) = pack_bf16x2(v0 - h0, v1 - h1);
        }
    }
}

// ---------------------------------------------------------------------------
// Launch
// ---------------------------------------------------------------------------
extern "C" void kernel_launch(void* const* d_in, const int* in_sizes, int n_in,
                              void* d_out, int out_size)
{
    const float* X  = (const float*)d_in[0];
    const float* Wq = (const float*)d_in[1];
    const float* Wk = (const float*)d_in[2];
    const float* Wv = (const float*)d_in[3];
    const float* Wo = (const float*)d_in[4];
    float* out = (float*)d_out;

    cudaFuncSetAttribute(qkv_gemm_fused, cudaFuncAttributeMaxDynamicSharedMemorySize, GEMM_SMEM);
    cudaFuncSetAttribute(out_gemm, cudaFuncAttributeMaxDynamicSharedMemorySize, GEMM_SMEM);
    cudaFuncSetAttribute(mha_fa_mma, cudaFuncAttributeMaxDynamicSharedMemorySize, ATT_SMEM);

    const int nElem = S_LEN * D_MODEL;

    // 1) split X; transpose+split weights
    split_x_kernel<<<nElem / 256, 256>>>(X);
    dim3 wb(32, 8), wg(D_MODEL / 32, D_MODEL / 32, 4);
    wsplit_t_kernel<<<wg, wb>>>(Wq, Wk, Wv, Wo);

    // 2) fused QKV projections (Q/K write bf16 splits directly; V fp32)
    dim3 gq(D_MODEL / 128, S_LEN / 128, 3);
    qkv_gemm_fused<<<gq, 256, GEMM_SMEM>>>();

    // 3) V transpose+split for attention
    dim3 vb(32, 8), vg(D_MODEL / 32, S_LEN / 32);
    vt_split_kernel<<<vg, vb>>>();

    // 4) causal flash attention on tensor cores (writes O bf16 splits)
    dim3 gatt(S_LEN / AQ, N_HEADS);
    mha_fa_mma<<<gatt, 256, ATT_SMEM>>>();

    // 5) output projection straight to harness buffer
    dim3 go(D_MODEL / 128, S_LEN / 128);
    out_gemm<<<go, 256, GEMM_SMEM>>>(out);
}

// round 12
// speedup vs baseline: 2.9336x; 1.0295x over previous
#include <cuda_runtime.h>
#include <cuda_bf16.h>
#include <math.h>
#include <stdint.h>

// Problem constants (fixed by the reference: B=1, S=4096, D=2048, H=16)
#define S_LEN    4096
#define D_MODEL  2048
#define KDIM     2048
#define N_HEADS  16
#define HEAD_DIM 128

// ---------------------------------------------------------------------------
// Scratch (__device__ globals; allocation-free rule)
// ---------------------------------------------------------------------------
__device__ float g_V[(size_t)S_LEN * D_MODEL];

__device__ __nv_bfloat16 g_Xhi[(size_t)S_LEN * D_MODEL];
__device__ __nv_bfloat16 g_Xlo[(size_t)S_LEN * D_MODEL];
__device__ __nv_bfloat16 g_Ohi[(size_t)S_LEN * D_MODEL];
__device__ __nv_bfloat16 g_Olo[(size_t)S_LEN * D_MODEL];
__device__ __nv_bfloat16 g_Wthi[(size_t)4 * D_MODEL * D_MODEL];
__device__ __nv_bfloat16 g_Wtlo[(size_t)4 * D_MODEL * D_MODEL];

// attention operands (bf16 hi/lo). Q pre-scaled by 1/sqrt(hd).
__device__ __nv_bfloat16 g_Qhi[(size_t)S_LEN * D_MODEL];
__device__ __nv_bfloat16 g_Qlo[(size_t)S_LEN * D_MODEL];
__device__ __nv_bfloat16 g_Khi[(size_t)S_LEN * D_MODEL];
__device__ __nv_bfloat16 g_Klo[(size_t)S_LEN * D_MODEL];
// V transposed per head: Vt[c][s] where c = h*128 + d  -> [D_MODEL][S_LEN]
__device__ __nv_bfloat16 g_Vthi[(size_t)D_MODEL * S_LEN];
__device__ __nv_bfloat16 g_Vtlo[(size_t)D_MODEL * S_LEN];

// ---------------------------------------------------------------------------
// Portable helpers (sm_80+): cp.async + mma.sync bf16
// ---------------------------------------------------------------------------
__device__ __forceinline__ uint32_t smem_to_u32(const void* p) {
    uint32_t a;
    asm("{ .reg .u64 t; cvta.to.shared.u64 t, %1; cvt.u32.u64 %0, t; }" : "=r"(a) : "l"(p));
    return a;
}
__device__ __forceinline__ void cp_async16(uint32_t dst, const void* src) {
    asm volatile("cp.async.cg.shared.global [%0], [%1], 16;" :: "r"(dst), "l"(src));
}
#define CP_COMMIT() asm volatile("cp.async.commit_group;" ::: "memory")
#define CP_WAIT1()  asm volatile("cp.async.wait_group 1;" ::: "memory")
#define CP_WAIT0()  asm volatile("cp.async.wait_group 0;" ::: "memory")

__device__ __forceinline__ void mma_bf16(float* c, const uint32_t* a, const uint32_t* b) {
    asm volatile(
        "mma.sync.aligned.m16n8k16.row.col.f32.bf16.bf16.f32 "
        "{%0,%1,%2,%3}, {%4,%5,%6,%7}, {%8,%9}, {%0,%1,%2,%3};"
        : "+f"(c[0]), "+f"(c[1]), "+f"(c[2]), "+f"(c[3])
        : "r"(a[0]), "r"(a[1]), "r"(a[2]), "r"(a[3]), "r"(b[0]), "r"(b[1]));
}
__device__ __forceinline__ uint32_t pack_bf16x2(float lo, float hi) {
    __nv_bfloat162 v = __float22bfloat162_rn(make_float2(lo, hi));
    return *reinterpret_cast<uint32_t*>(&v);
}

// ---------------------------------------------------------------------------
// Prep kernels
// ---------------------------------------------------------------------------
__global__ void split_x_kernel(const float* __restrict__ X) {
    size_t i = (size_t)blockIdx.x * blockDim.x + threadIdx.x;
    float v = X[i];
    __nv_bfloat16 h = __float2bfloat16(v);
    g_Xhi[i] = h;
    g_Xlo[i] = __float2bfloat16(v - __bfloat162float(h));
}
__global__ void wsplit_t_kernel(const float* __restrict__ Wq, const float* __restrict__ Wk,
                                const float* __restrict__ Wv, const float* __restrict__ Wo) {
    __shared__ float tile[32][33];
    const int w = blockIdx.z;
    const float* W = (w == 0) ? Wq : (w == 1) ? Wk : (w == 2) ? Wv : Wo;
    const size_t off = (size_t)w * D_MODEL * D_MODEL;
    const int n0 = blockIdx.x * 32, k0 = blockIdx.y * 32;
    const int tx = threadIdx.x, ty = threadIdx.y;  // (32, 8)
#pragma unroll
    for (int i = 0; i < 32; i += 8)
        tile[ty + i][tx] = W[(size_t)(k0 + ty + i) * D_MODEL + n0 + tx];
    __syncthreads();
#pragma unroll
    for (int i = 0; i < 32; i += 8) {
        int n = n0 + ty + i, k = k0 + tx;
        float v = tile[tx][ty + i];
        __nv_bfloat16 h = __float2bfloat16(v);
        g_Wthi[off + (size_t)n * KDIM + k] = h;
        g_Wtlo[off + (size_t)n * KDIM + k] = __float2bfloat16(v - __bfloat162float(h));
    }
}
// V [S][D] fp32 -> Vt hi/lo [D][S] bf16 (coalesced 32x32 transpose)
__global__ void vt_split_kernel() {
    __shared__ float tile[32][33];
    const int s0 = blockIdx.y * 32, c0 = blockIdx.x * 32;
    const int tx = threadIdx.x, ty = threadIdx.y;  // (32, 8)
#pragma unroll
    for (int i = 0; i < 32; i += 8)
        tile[ty + i][tx] = g_V[(size_t)(s0 + ty + i) * D_MODEL + c0 + tx];
    __syncthreads();
#pragma unroll
    for (int i = 0; i < 32; i += 8) {
        int c = c0 + ty + i, s = s0 + tx;
        float v = tile[tx][ty + i];
        __nv_bfloat16 h = __float2bfloat16(v);
        g_Vthi[(size_t)c * S_LEN + s] = h;
        g_Vtlo[(size_t)c * S_LEN + s] = __float2bfloat16(v - __bfloat162float(h));
    }
}

// ---------------------------------------------------------------------------
// bf16x3 tensor-core GEMM core (compute accumulators for one 128x128 tile).
// Block 128x128xK32, 256 threads (8 warps 2x4), warp tile 64x32.
// ---------------------------------------------------------------------------
#define LDSW 40
#define TILE_B (128 * LDSW * 2)
#define STAGE_B (4 * TILE_B)
#define GEMM_SMEM (2 * STAGE_B)
#define NSTAGE (KDIM / 32)

__device__ __forceinline__ void gemm_core(const __nv_bfloat16* __restrict__ Ah,
                                          const __nv_bfloat16* __restrict__ Al,
                                          const __nv_bfloat16* __restrict__ Bh,
                                          const __nv_bfloat16* __restrict__ Bl,
                                          char* sm_, float acc[4][4][4])
{
    const int t = threadIdx.x;
    const int lane = t & 31, wid = t >> 5;
    const int wm = wid >> 2, wn = wid & 3;
    const uint32_t sbase = smem_to_u32(sm_);

#pragma unroll
    for (int mi = 0; mi < 4; mi++)
#pragma unroll
        for (int ni = 0; ni < 4; ni++)
#pragma unroll
            for (int e = 0; e < 4; e++) acc[mi][ni][e] = 0.0f;

    const int ldr = t >> 2;
    const int kc  = t & 3;
    const __nv_bfloat16* srcs[4] = { Ah, Al, Bh, Bl };

    {
        const uint32_t dbase = sbase;
#pragma unroll
        for (int j = 0; j < 8; j++) {
            const int tile = j >> 1;
            const int row = (j & 1) * 64 + ldr;
            cp_async16(dbase + tile * TILE_B + row * 80 + kc * 16,
                       srcs[tile] + (size_t)row * KDIM + kc * 8);
        }
        CP_COMMIT();
    }

    for (int kt = 0; kt < NSTAGE; kt++) {
        if (kt + 1 < NSTAGE) {
            const int k0 = (kt + 1) * 32;
            const uint32_t dbase = sbase + ((kt + 1) & 1) * STAGE_B;
#pragma unroll
            for (int j = 0; j < 8; j++) {
                const int tile = j >> 1;
                const int row = (j & 1) * 64 + ldr;
                cp_async16(dbase + tile * TILE_B + row * 80 + kc * 16,
                           srcs[tile] + (size_t)row * KDIM + k0 + kc * 8);
            }
            CP_COMMIT();
            CP_WAIT1();
        } else {
            CP_WAIT0();
        }
        __syncthreads();

        const char* st = sm_ + (kt & 1) * STAGE_B;
        const __nv_bfloat16* sAh = (const __nv_bfloat16*)(st);
        const __nv_bfloat16* sAl = (const __nv_bfloat16*)(st + TILE_B);
        const __nv_bfloat16* sBh = (const __nv_bfloat16*)(st + 2 * TILE_B);
        const __nv_bfloat16* sBl = (const __nv_bfloat16*)(st + 3 * TILE_B);

#pragma unroll
        for (int ks = 0; ks < 2; ks++) {
            const int kk = ks * 16 + (lane & 3) * 2;
            const int rsub = lane >> 2;

            uint32_t ah[4][4], al[4][4], bh[4][2], bl[4][2];
#pragma unroll
            for (int mi = 0; mi < 4; mi++) {
                const int r0 = wm * 64 + mi * 16 + rsub;
                const uint32_t* p0h = (const uint32_t*)(sAh + r0 * LDSW + kk);
                const uint32_t* p1h = (const uint32_t*)(sAh + (r0 + 8) * LDSW + kk);
                ah[mi][0] = p0h[0]; ah[mi][1] = p1h[0]; ah[mi][2] = p0h[4]; ah[mi][3] = p1h[4];
                const uint32_t* p0l = (const uint32_t*)(sAl + r0 * LDSW + kk);
                const uint32_t* p1l = (const uint32_t*)(sAl + (r0 + 8) * LDSW + kk);
                al[mi][0] = p0l[0]; al[mi][1] = p1l[0]; al[mi][2] = p0l[4]; al[mi][3] = p1l[4];
            }
#pragma unroll
            for (int ni = 0; ni < 4; ni++) {
                const int rn = wn * 32 + ni * 8 + rsub;
                const uint32_t* pbh = (const uint32_t*)(sBh + rn * LDSW + kk);
                bh[ni][0] = pbh[0]; bh[ni][1] = pbh[4];
                const uint32_t* pbl = (const uint32_t*)(sBl + rn * LDSW + kk);
                bl[ni][0] = pbl[0]; bl[ni][1] = pbl[4];
            }
#pragma unroll
            for (int mi = 0; mi < 4; mi++)
#pragma unroll
                for (int ni = 0; ni < 4; ni++) {
                    mma_bf16(acc[mi][ni], ah[mi], bh[ni]);
                    mma_bf16(acc[mi][ni], ah[mi], bl[ni]);
                    mma_bf16(acc[mi][ni], al[mi], bh[ni]);
                }
        }
        __syncthreads();
    }
}

// Fused QKV: z=0 -> Q (scaled, bf16 split out), z=1 -> K (split out), z=2 -> V (fp32)
__global__ __launch_bounds__(256, 2)
void qkv_gemm_fused()
{
    extern __shared__ char sm_[];
    const int z = blockIdx.z;
    const int bm = blockIdx.y, bn = blockIdx.x;
    const size_t woff = (size_t)z * D_MODEL * D_MODEL;

    float acc[4][4][4];
    gemm_core(g_Xhi + (size_t)(bm * 128) * KDIM,
              g_Xlo + (size_t)(bm * 128) * KDIM,
              g_Wthi + woff + (size_t)(bn * 128) * KDIM,
              g_Wtlo + woff + (size_t)(bn * 128) * KDIM,
              sm_, acc);

    const int t = threadIdx.x;
    const int lane = t & 31, wid = t >> 5;
    const int wm = wid >> 2, wn = wid & 3;
    const int rsub = lane >> 2, csub = (lane & 3) * 2;
    const int rowB = bm * 128 + wm * 64;
    const int colB = bn * 128 + wn * 32;

    if (z == 2) {
        float* Cb = g_V + (size_t)rowB * D_MODEL + colB;
#pragma unroll
        for (int mi = 0; mi < 4; mi++)
#pragma unroll
            for (int ni = 0; ni < 4; ni++) {
                const int row = mi * 16 + rsub;
                const int col = ni * 8 + csub;
                *reinterpret_cast<float2*>(Cb + (size_t)row * D_MODEL + col) =
                    make_float2(acc[mi][ni][0], acc[mi][ni][1]);
                *reinterpret_cast<float2*>(Cb + (size_t)(row + 8) * D_MODEL + col) =
                    make_float2(acc[mi][ni][2], acc[mi][ni][3]);
            }
    } else {
        const float scale = (z == 0) ? 0.08838834764831845f : 1.0f;
        __nv_bfloat16* Hi = (z == 0) ? g_Qhi : g_Khi;
        __nv_bfloat16* Lo = (z == 0) ? g_Qlo : g_Klo;
#pragma unroll
        for (int mi = 0; mi < 4; mi++)
#pragma unroll
            for (int ni = 0; ni < 4; ni++) {
                const int row = rowB + mi * 16 + rsub;
                const int col = colB + ni * 8 + csub;
#pragma unroll
                for (int half = 0; half < 2; half++) {
                    const int r = row + half * 8;
                    float v0 = acc[mi][ni][2 * half + 0] * scale;
                    float v1 = acc[mi][ni][2 * half + 1] * scale;
                    float h0 = __bfloat162float(__float2bfloat16(v0));
                    float h1 = __bfloat162float(__float2bfloat16(v1));
                    *reinterpret_cast<uint32_t*>(Hi + (size_t)r * D_MODEL + col) =
                        pack_bf16x2(h0, h1);
                    *reinterpret_cast<uint32_t*>(Lo + (size_t)r * D_MODEL + col) =
                        pack_bf16x2(v0 - h0, v1 - h1);
                }
            }
    }
}

// Output projection: fp32 epilogue straight to harness output
__global__ __launch_bounds__(256, 2)
void out_gemm(float* __restrict__ out)
{
    extern __shared__ char sm_[];
    const int bm = blockIdx.y, bn = blockIdx.x;
    const size_t woff = (size_t)3 * D_MODEL * D_MODEL;

    float acc[4][4][4];
    gemm_core(g_Ohi + (size_t)(bm * 128) * KDIM,
              g_Olo + (size_t)(bm * 128) * KDIM,
              g_Wthi + woff + (size_t)(bn * 128) * KDIM,
              g_Wtlo + woff + (size_t)(bn * 128) * KDIM,
              sm_, acc);

    const int t = threadIdx.x;
    const int lane = t & 31, wid = t >> 5;
    const int wm = wid >> 2, wn = wid & 3;
    const int rsub = lane >> 2, csub = (lane & 3) * 2;

    float* Cb = out + (size_t)(bm * 128 + wm * 64) * D_MODEL + bn * 128 + wn * 32;
#pragma unroll
    for (int mi = 0; mi < 4; mi++)
#pragma unroll
        for (int ni = 0; ni < 4; ni++) {
            const int row = mi * 16 + rsub;
            const int col = ni * 8 + csub;
            *reinterpret_cast<float2*>(Cb + (size_t)row * D_MODEL + col) =
                make_float2(acc[mi][ni][0], acc[mi][ni][1]);
            *reinterpret_cast<float2*>(Cb + (size_t)(row + 8) * D_MODEL + col) =
                make_float2(acc[mi][ni][2], acc[mi][ni][3]);
        }
}

// ---------------------------------------------------------------------------
// FA2-style attention on mma.sync (bf16 split precision).
// CTA = 128 queries x 1 head, 256 threads, 8 warps x 16 query rows.
// KV tiles of 64 keys, DOUBLE-BUFFERED via cp.async (load jb+1 overlaps
// compute of jb). Online softmax in fp32; P kept in registers.
// Epilogue writes O directly as bf16 hi/lo splits.
// ---------------------------------------------------------------------------
#define AQ 128
#define AK 64
#define QSTR 136   // bf16 elems per Q/K smem row (272 B) -> conflict-free
#define VSTR 72    // bf16 elems per Vt smem row (144 B) -> conflict-free

#define SM_QHI 0
#define SM_QLO (SM_QHI + AQ * QSTR * 2)          // 34816
#define SM_KV  (SM_QLO + AQ * QSTR * 2)          // 69632: start of KV stages
#define KV_KHI 0
#define KV_KLO (KV_KHI + AK * QSTR * 2)          // 17408
#define KV_VHI (KV_KLO + AK * QSTR * 2)          // 34816
#define KV_VLO (KV_VHI + HEAD_DIM * VSTR * 2)    // 53248
#define KV_STAGE (KV_VLO + HEAD_DIM * VSTR * 2)  // 71680
#define ATT_SMEM (SM_KV + 2 * KV_STAGE)          // 212992

__global__ __launch_bounds__(256, 1)
void mha_fa_mma()
{
    extern __shared__ char sm_[];
    const uint32_t sbase = smem_to_u32(sm_);
    const int t = threadIdx.x;
    const int lane = t & 31, wid = t >> 5;
    const int ib = gridDim.x - 1 - blockIdx.x;   // reversed: long CTAs first
    const int h = blockIdx.y;
    const int q0 = ib * AQ;
    const int rsub = lane >> 2, csub = (lane & 3) * 2;
    const int kk = csub;

    const __nv_bfloat16* sQh = (const __nv_bfloat16*)(sm_ + SM_QHI);
    const __nv_bfloat16* sQl = (const __nv_bfloat16*)(sm_ + SM_QLO);

    // ---- load Q tile (once), group 0 ----
    {
        const size_t gq = (size_t)q0 * D_MODEL + (size_t)h * HEAD_DIM;
#pragma unroll
        for (int i = 0; i < 8; i++) {
            const int idx = t + i * 256;
            const int row = idx >> 4, c = idx & 15;
            cp_async16(sbase + SM_QHI + row * (QSTR * 2) + c * 16,
                       g_Qhi + gq + (size_t)row * D_MODEL + c * 8);
            cp_async16(sbase + SM_QLO + row * (QSTR * 2) + c * 16,
                       g_Qlo + gq + (size_t)row * D_MODEL + c * 8);
        }
        CP_COMMIT();
    }

    const int nTiles = 2 * ib + 2;

    // ---- helper lambda: issue K/V loads for tile jb into given stage ----
    auto load_kv = [&](int jb, int stage) {
        const uint32_t kvb = sbase + SM_KV + stage * KV_STAGE;
        const int k0 = jb * AK;
        const size_t gk = (size_t)k0 * D_MODEL + (size_t)h * HEAD_DIM;
#pragma unroll
        for (int i = 0; i < 4; i++) {
            const int idx = t + i * 256;
            const int row = idx >> 4, c = idx & 15;
            cp_async16(kvb + KV_KHI + row * (QSTR * 2) + c * 16,
                       g_Khi + gk + (size_t)row * D_MODEL + c * 8);
            cp_async16(kvb + KV_KLO + row * (QSTR * 2) + c * 16,
                       g_Klo + gk + (size_t)row * D_MODEL + c * 8);
        }
        const size_t gv = (size_t)h * HEAD_DIM * S_LEN + k0;
#pragma unroll
        for (int i = 0; i < 4; i++) {
            const int idx = t + i * 256;
            const int row = idx >> 3, c = idx & 7;
            cp_async16(kvb + KV_VHI + row * (VSTR * 2) + c * 16,
                       g_Vthi + gv + (size_t)row * S_LEN + c * 8);
            cp_async16(kvb + KV_VLO + row * (VSTR * 2) + c * 16,
                       g_Vtlo + gv + (size_t)row * S_LEN + c * 8);
        }
        CP_COMMIT();
    };

    // preload tile 0 into stage 0 (group 1)
    load_kv(0, 0);

    float accO[16][4];
#pragma unroll
    for (int j = 0; j < 16; j++)
#pragma unroll
        for (int e = 0; e < 4; e++) accO[j][e] = 0.0f;
    float m0 = -1e30f, m1 = -1e30f, l0 = 0.0f, l1 = 0.0f;

    for (int jb = 0; jb < nTiles; jb++) {
        const int buf = jb & 1;
        // prefetch next tile into alternate stage, then wait for current tile
        if (jb + 1 < nTiles) {
            load_kv(jb + 1, buf ^ 1);
            CP_WAIT1();           // current tile (and Q) complete; next in flight
        } else {
            CP_WAIT0();
        }
        __syncthreads();

        const char* kvb = sm_ + SM_KV + buf * KV_STAGE;
        const __nv_bfloat16* sKh = (const __nv_bfloat16*)(kvb + KV_KHI);
        const __nv_bfloat16* sKl = (const __nv_bfloat16*)(kvb + KV_KLO);
        const __nv_bfloat16* sVh = (const __nv_bfloat16*)(kvb + KV_VHI);
        const __nv_bfloat16* sVl = (const __nv_bfloat16*)(kvb + KV_VLO);
        const int k0 = jb * AK;

        // ---- S = Q K^T (bf16x3) ----
        float accS[8][4];
#pragma unroll
        for (int j = 0; j < 8; j++)
#pragma unroll
            for (int e = 0; e < 4; e++) accS[j][e] = 0.0f;

#pragma unroll
        for (int ks = 0; ks < 8; ks++) {
            const int kc = ks * 16 + kk;
            uint32_t ah[4], al[4];
            {
                const int r0 = wid * 16 + rsub;
                const uint32_t* p0h = (const uint32_t*)(sQh + r0 * QSTR + kc);
                const uint32_t* p1h = (const uint32_t*)(sQh + (r0 + 8) * QSTR + kc);
                ah[0] = p0h[0]; ah[1] = p1h[0]; ah[2] = p0h[4]; ah[3] = p1h[4];
                const uint32_t* p0l = (const uint32_t*)(sQl + r0 * QSTR + kc);
                const uint32_t* p1l = (const uint32_t*)(sQl + (r0 + 8) * QSTR + kc);
                al[0] = p0l[0]; al[1] = p1l[0]; al[2] = p0l[4]; al[3] = p1l[4];
            }
#pragma unroll
            for (int j = 0; j < 8; j++) {
                const int rn = j * 8 + rsub;
                uint32_t bh[2], bl[2];
                const uint32_t* pbh = (const uint32_t*)(sKh + rn * QSTR + kc);
                bh[0] = pbh[0]; bh[1] = pbh[4];
                const uint32_t* pbl = (const uint32_t*)(sKl + rn * QSTR + kc);
                bl[0] = pbl[0]; bl[1] = pbl[4];
                mma_bf16(accS[j], ah, bh);
                mma_bf16(accS[j], ah, bl);
                mma_bf16(accS[j], al, bh);
            }
        }

        // ---- causal mask (only the two diagonal tiles) ----
        if (jb >= 2 * ib) {
            const int row0 = q0 + wid * 16 + rsub;
            const int row1 = row0 + 8;
#pragma unroll
            for (int j = 0; j < 8; j++) {
                const int c0 = k0 + j * 8 + csub;
                if (c0 > row0)     accS[j][0] = -1e30f;
                if (c0 + 1 > row0) accS[j][1] = -1e30f;
                if (c0 > row1)     accS[j][2] = -1e30f;
                if (c0 + 1 > row1) accS[j][3] = -1e30f;
            }
        }

        // ---- online softmax ----
        float mx0 = -1e30f, mx1 = -1e30f;
#pragma unroll
        for (int j = 0; j < 8; j++) {
            mx0 = fmaxf(mx0, fmaxf(accS[j][0], accS[j][1]));
            mx1 = fmaxf(mx1, fmaxf(accS[j][2], accS[j][3]));
        }
        mx0 = fmaxf(mx0, __shfl_xor_sync(0xffffffffu, mx0, 1));
        mx0 = fmaxf(mx0, __shfl_xor_sync(0xffffffffu, mx0, 2));
        mx1 = fmaxf(mx1, __shfl_xor_sync(0xffffffffu, mx1, 1));
        mx1 = fmaxf(mx1, __shfl_xor_sync(0xffffffffu, mx1, 2));

        const float mn0 = fmaxf(m0, mx0);
        const float mn1 = fmaxf(m1, mx1);
        const float al0 = __expf(m0 - mn0);
        const float al1 = __expf(m1 - mn1);
        m0 = mn0; m1 = mn1;

        float s0 = 0.0f, s1 = 0.0f;
#pragma unroll
        for (int j = 0; j < 8; j++) {
            accS[j][0] = __expf(accS[j][0] - m0);
            accS[j][1] = __expf(accS[j][1] - m0);
            accS[j][2] = __expf(accS[j][2] - m1);
            accS[j][3] = __expf(accS[j][3] - m1);
            s0 += accS[j][0] + accS[j][1];
            s1 += accS[j][2] + accS[j][3];
        }
        s0 += __shfl_xor_sync(0xffffffffu, s0, 1);
        s0 += __shfl_xor_sync(0xffffffffu, s0, 2);
        s1 += __shfl_xor_sync(0xffffffffu, s1, 1);
        s1 += __shfl_xor_sync(0xffffffffu, s1, 2);
        l0 = l0 * al0 + s0;
        l1 = l1 * al1 + s1;

#pragma unroll
        for (int j = 0; j < 16; j++) {
            accO[j][0] *= al0; accO[j][1] *= al0;
            accO[j][2] *= al1; accO[j][3] *= al1;
        }

        // ---- O += P V (bf16x3; P fragments straight from accS) ----
#pragma unroll
        for (int ks = 0; ks < 4; ks++) {
            uint32_t ph[4], pl[4];
            {
                const float* f0 = accS[2 * ks];
                const float* f1 = accS[2 * ks + 1];
                float h00 = __bfloat162float(__float2bfloat16(f0[0]));
                float h01 = __bfloat162float(__float2bfloat16(f0[1]));
                float h02 = __bfloat162float(__float2bfloat16(f0[2]));
                float h03 = __bfloat162float(__float2bfloat16(f0[3]));
                float h10 = __bfloat162float(__float2bfloat16(f1[0]));
                float h11 = __bfloat162float(__float2bfloat16(f1[1]));
                float h12 = __bfloat162float(__float2bfloat16(f1[2]));
                float h13 = __bfloat162float(__float2bfloat16(f1[3]));
                ph[0] = pack_bf16x2(h00, h01);
                ph[1] = pack_bf16x2(h02, h03);
                ph[2] = pack_bf16x2(h10, h11);
                ph[3] = pack_bf16x2(h12, h13);
                pl[0] = pack_bf16x2(f0[0] - h00, f0[1] - h01);
                pl[1] = pack_bf16x2(f0[2] - h02, f0[3] - h03);
                pl[2] = pack_bf16x2(f1[0] - h10, f1[1] - h11);
                pl[3] = pack_bf16x2(f1[2] - h12, f1[3] - h13);
            }
            const int kc = ks * 16 + kk;
#pragma unroll
            for (int j = 0; j < 16; j++) {
                const int rn = j * 8 + rsub;
                uint32_t bvh[2], bvl[2];
                const uint32_t* pvh = (const uint32_t*)(sVh + rn * VSTR + kc);
                bvh[0] = pvh[0]; bvh[1] = pvh[4];
                const uint32_t* pvl = (const uint32_t*)(sVl + rn * VSTR + kc);
                bvl[0] = pvl[0]; bvl[1] = pvl[4];
                mma_bf16(accO[j], ph, bvh);
                mma_bf16(accO[j], ph, bvl);
                mma_bf16(accO[j], pl, bvh);
            }
        }
        __syncthreads();   // all warps done reading this stage before it is re-filled
    }

    // ---- normalize + write O directly as bf16 hi/lo splits ----
    const float inv0 = 1.0f / l0;
    const float inv1 = 1.0f / l1;
    const size_t obase = (size_t)(q0 + wid * 16 + rsub) * D_MODEL + (size_t)h * HEAD_DIM;
#pragma unroll
    for (int j = 0; j < 16; j++) {
        const int col = j * 8 + csub;
#pragma unroll
        for (int half = 0; half < 2; half++) {
            const size_t off = obase + (size_t)(half * 8) * D_MODEL + col;
            float v0 = accO[j][2 * half + 0] * (half ? inv1 : inv0);
            float v1 = accO[j][2 * half + 1] * (half ? inv1 : inv0);
            float h0 = __bfloat162float(__float2bfloat16(v0));
            float h1 = __bfloat162float(__float2bfloat16(v1));
            *reinterpret_cast<uint32_t*>(g_Ohi + off) = pack_bf16x2(h0, h1);
            *reinterpret_cast<uint32_t*>(g_Olo + off) = pack_bf16x2(v0 - h0, v1 - h1);
        }
    }
}

// ---------------------------------------------------------------------------
// Launch
// ---------------------------------------------------------------------------
extern "C" void kernel_launch(void* const* d_in, const int* in_sizes, int n_in,
                              void* d_out, int out_size)
{
    const float* X  = (const float*)d_in[0];
    const float* Wq = (const float*)d_in[1];
    const float* Wk = (const float*)d_in[2];
    const float* Wv = (const float*)d_in[3];
    const float* Wo = (const float*)d_in[4];
    float* out = (float*)d_out;

    cudaFuncSetAttribute(qkv_gemm_fused, cudaFuncAttributeMaxDynamicSharedMemorySize, GEMM_SMEM);
    cudaFuncSetAttribute(out_gemm, cudaFuncAttributeMaxDynamicSharedMemorySize, GEMM_SMEM);
    cudaFuncSetAttribute(mha_fa_mma, cudaFuncAttributeMaxDynamicSharedMemorySize, ATT_SMEM);

    const int nElem = S_LEN * D_MODEL;

    // 1) split X; transpose+split weights
    split_x_kernel<<<nElem / 256, 256>>>(X);
    dim3 wb(32, 8), wg(D_MODEL / 32, D_MODEL / 32, 4);
    wsplit_t_kernel<<<wg, wb>>>(Wq, Wk, Wv, Wo);

    // 2) fused QKV projections (Q/K write bf16 splits directly; V fp32)
    dim3 gq(D_MODEL / 128, S_LEN / 128, 3);
    qkv_gemm_fused<<<gq, 256, GEMM_SMEM>>>();

    // 3) V transpose+split for attention
    dim3 vb(32, 8), vg(D_MODEL / 32, S_LEN / 32);
    vt_split_kernel<<<vg, vb>>>();

    // 4) causal flash attention on tensor cores (double-buffered K/V)
    dim3 gatt(S_LEN / AQ, N_HEADS);
    mha_fa_mma<<<gatt, 256, ATT_SMEM>>>();

    // 5) output projection straight to harness buffer
    dim3 go(D_MODEL / 128, S_LEN / 128);
    out_gemm<<<go, 256, GEMM_SMEM>>>(out);
}

// round 13
// speedup vs baseline: 3.1271x; 1.0659x over previous
#include <cuda_runtime.h>
#include <cuda_bf16.h>
#include <math.h>
#include <stdint.h>

// Problem constants (fixed by the reference: B=1, S=4096, D=2048, H=16)
#define S_LEN    4096
#define D_MODEL  2048
#define KDIM     2048
#define N_HEADS  16
#define HEAD_DIM 128

// ---------------------------------------------------------------------------
// Scratch (__device__ globals; allocation-free rule)
// ---------------------------------------------------------------------------
__device__ float g_V[(size_t)S_LEN * D_MODEL];

__device__ __nv_bfloat16 g_Xhi[(size_t)S_LEN * D_MODEL];
__device__ __nv_bfloat16 g_Xlo[(size_t)S_LEN * D_MODEL];
__device__ __nv_bfloat16 g_Ohi[(size_t)S_LEN * D_MODEL];
__device__ __nv_bfloat16 g_Olo[(size_t)S_LEN * D_MODEL];
__device__ __nv_bfloat16 g_Wthi[(size_t)4 * D_MODEL * D_MODEL];
__device__ __nv_bfloat16 g_Wtlo[(size_t)4 * D_MODEL * D_MODEL];

// attention operands (bf16 hi/lo). Q pre-scaled by 1/sqrt(hd).
__device__ __nv_bfloat16 g_Qhi[(size_t)S_LEN * D_MODEL];
__device__ __nv_bfloat16 g_Qlo[(size_t)S_LEN * D_MODEL];
__device__ __nv_bfloat16 g_Khi[(size_t)S_LEN * D_MODEL];
__device__ __nv_bfloat16 g_Klo[(size_t)S_LEN * D_MODEL];
// V transposed per head: Vt[c][s] where c = h*128 + d  -> [D_MODEL][S_LEN]
__device__ __nv_bfloat16 g_Vthi[(size_t)D_MODEL * S_LEN];
__device__ __nv_bfloat16 g_Vtlo[(size_t)D_MODEL * S_LEN];

// ---------------------------------------------------------------------------
// Portable helpers (sm_80+): cp.async + mma.sync bf16 + ldmatrix
// ---------------------------------------------------------------------------
__device__ __forceinline__ uint32_t smem_to_u32(const void* p) {
    uint32_t a;
    asm("{ .reg .u64 t; cvta.to.shared.u64 t, %1; cvt.u32.u64 %0, t; }" : "=r"(a) : "l"(p));
    return a;
}
__device__ __forceinline__ void cp_async16(uint32_t dst, const void* src) {
    asm volatile("cp.async.cg.shared.global [%0], [%1], 16;" :: "r"(dst), "l"(src));
}
#define CP_COMMIT() asm volatile("cp.async.commit_group;" ::: "memory")
#define CP_WAIT1()  asm volatile("cp.async.wait_group 1;" ::: "memory")
#define CP_WAIT0()  asm volatile("cp.async.wait_group 0;" ::: "memory")

__device__ __forceinline__ void mma_bf16(float* c, const uint32_t* a, const uint32_t* b) {
    asm volatile(
        "mma.sync.aligned.m16n8k16.row.col.f32.bf16.bf16.f32 "
        "{%0,%1,%2,%3}, {%4,%5,%6,%7}, {%8,%9}, {%0,%1,%2,%3};"
        : "+f"(c[0]), "+f"(c[1]), "+f"(c[2]), "+f"(c[3])
        : "r"(a[0]), "r"(a[1]), "r"(a[2]), "r"(a[3]), "r"(b[0]), "r"(b[1]));
}
__device__ __forceinline__ void ldsm_x4(uint32_t& r0, uint32_t& r1, uint32_t& r2, uint32_t& r3,
                                        uint32_t addr) {
    asm volatile("ldmatrix.sync.aligned.m8n8.x4.shared.b16 {%0,%1,%2,%3}, [%4];"
                 : "=r"(r0), "=r"(r1), "=r"(r2), "=r"(r3) : "r"(addr));
}
__device__ __forceinline__ uint32_t pack_bf16x2(float lo, float hi) {
    __nv_bfloat162 v = __float22bfloat162_rn(make_float2(lo, hi));
    return *reinterpret_cast<uint32_t*>(&v);
}

// ---------------------------------------------------------------------------
// Prep kernels
// ---------------------------------------------------------------------------
__global__ void split_x_kernel(const float* __restrict__ X) {
    size_t i = (size_t)blockIdx.x * blockDim.x + threadIdx.x;
    float v = X[i];
    __nv_bfloat16 h = __float2bfloat16(v);
    g_Xhi[i] = h;
    g_Xlo[i] = __float2bfloat16(v - __bfloat162float(h));
}
__global__ void wsplit_t_kernel(const float* __restrict__ Wq, const float* __restrict__ Wk,
                                const float* __restrict__ Wv, const float* __restrict__ Wo) {
    __shared__ float tile[32][33];
    const int w = blockIdx.z;
    const float* W = (w == 0) ? Wq : (w == 1) ? Wk : (w == 2) ? Wv : Wo;
    const size_t off = (size_t)w * D_MODEL * D_MODEL;
    const int n0 = blockIdx.x * 32, k0 = blockIdx.y * 32;
    const int tx = threadIdx.x, ty = threadIdx.y;  // (32, 8)
#pragma unroll
    for (int i = 0; i < 32; i += 8)
        tile[ty + i][tx] = W[(size_t)(k0 + ty + i) * D_MODEL + n0 + tx];
    __syncthreads();
#pragma unroll
    for (int i = 0; i < 32; i += 8) {
        int n = n0 + ty + i, k = k0 + tx;
        float v = tile[tx][ty + i];
        __nv_bfloat16 h = __float2bfloat16(v);
        g_Wthi[off + (size_t)n * KDIM + k] = h;
        g_Wtlo[off + (size_t)n * KDIM + k] = __float2bfloat16(v - __bfloat162float(h));
    }
}
// V [S][D] fp32 -> Vt hi/lo [D][S] bf16 (coalesced 32x32 transpose)
__global__ void vt_split_kernel() {
    __shared__ float tile[32][33];
    const int s0 = blockIdx.y * 32, c0 = blockIdx.x * 32;
    const int tx = threadIdx.x, ty = threadIdx.y;  // (32, 8)
#pragma unroll
    for (int i = 0; i < 32; i += 8)
        tile[ty + i][tx] = g_V[(size_t)(s0 + ty + i) * D_MODEL + c0 + tx];
    __syncthreads();
#pragma unroll
    for (int i = 0; i < 32; i += 8) {
        int c = c0 + ty + i, s = s0 + tx;
        float v = tile[tx][ty + i];
        __nv_bfloat16 h = __float2bfloat16(v);
        g_Vthi[(size_t)c * S_LEN + s] = h;
        g_Vtlo[(size_t)c * S_LEN + s] = __float2bfloat16(v - __bfloat162float(h));
    }
}

// ---------------------------------------------------------------------------
// bf16x3 tensor-core GEMM core (compute accumulators for one 128x128 tile).
// Block 128x128xK32, 256 threads (8 warps 2x4), warp tile 64x32.
// Fragment loads via ldmatrix.x4 (12 LDSM/ks vs 48 LDS.32/ks).
// ---------------------------------------------------------------------------
#define LDSW 40
#define TILE_B (128 * LDSW * 2)
#define STAGE_B (4 * TILE_B)
#define GEMM_SMEM (2 * STAGE_B)
#define NSTAGE (KDIM / 32)

__device__ __forceinline__ void gemm_core(const __nv_bfloat16* __restrict__ Ah,
                                          const __nv_bfloat16* __restrict__ Al,
                                          const __nv_bfloat16* __restrict__ Bh,
                                          const __nv_bfloat16* __restrict__ Bl,
                                          char* sm_, float acc[4][4][4])
{
    const int t = threadIdx.x;
    const int lane = t & 31, wid = t >> 5;
    const int wm = wid >> 2, wn = wid & 3;
    const uint32_t sbase = smem_to_u32(sm_);

#pragma unroll
    for (int mi = 0; mi < 4; mi++)
#pragma unroll
        for (int ni = 0; ni < 4; ni++)
#pragma unroll
            for (int e = 0; e < 4; e++) acc[mi][ni][e] = 0.0f;

    const int ldr = t >> 2;
    const int kc  = t & 3;
    const __nv_bfloat16* srcs[4] = { Ah, Al, Bh, Bl };

    // ldmatrix lane-address components (per warp):
    const int lr = lane & 7;       // row within 8x8 matrix
    const int lg = lane >> 3;      // matrix group 0..3
    // A x4: groups -> (row r0+ (g&1)*8 + lr, kchunk (g>>1)*8)
    const int a_row_off = (lg & 1) * 8 + lr;
    const int a_col_off = (lg >> 1) * 8;
    // B x4: groups -> (row nb + ((g>>1)&1)*8 + lr, kchunk (g&1)*8)
    const int b_row_off = ((lg >> 1) & 1) * 8 + lr;
    const int b_col_off = (lg & 1) * 8;

    {
        const uint32_t dbase = sbase;
#pragma unroll
        for (int j = 0; j < 8; j++) {
            const int tile = j >> 1;
            const int row = (j & 1) * 64 + ldr;
            cp_async16(dbase + tile * TILE_B + row * 80 + kc * 16,
                       srcs[tile] + (size_t)row * KDIM + kc * 8);
        }
        CP_COMMIT();
    }

    for (int kt = 0; kt < NSTAGE; kt++) {
        if (kt + 1 < NSTAGE) {
            const int k0 = (kt + 1) * 32;
            const uint32_t dbase = sbase + ((kt + 1) & 1) * STAGE_B;
#pragma unroll
            for (int j = 0; j < 8; j++) {
                const int tile = j >> 1;
                const int row = (j & 1) * 64 + ldr;
                cp_async16(dbase + tile * TILE_B + row * 80 + kc * 16,
                           srcs[tile] + (size_t)row * KDIM + k0 + kc * 8);
            }
            CP_COMMIT();
            CP_WAIT1();
        } else {
            CP_WAIT0();
        }
        __syncthreads();

        const uint32_t stb = sbase + (kt & 1) * STAGE_B;
        const uint32_t sAh = stb;
        const uint32_t sAl = stb + TILE_B;
        const uint32_t sBh = stb + 2 * TILE_B;
        const uint32_t sBl = stb + 3 * TILE_B;

#pragma unroll
        for (int ks = 0; ks < 2; ks++) {
            const int kbase = ks * 16;

            uint32_t ah[4][4], al[4][4], bh[4][2], bl[4][2];
            // A fragments: one ldmatrix.x4 per mi per tile
#pragma unroll
            for (int mi = 0; mi < 4; mi++) {
                const int r = wm * 64 + mi * 16 + a_row_off;
                const uint32_t off = (uint32_t)(r * LDSW + kbase + a_col_off) * 2;
                ldsm_x4(ah[mi][0], ah[mi][1], ah[mi][2], ah[mi][3], sAh + off);
                ldsm_x4(al[mi][0], al[mi][1], al[mi][2], al[mi][3], sAl + off);
            }
            // B fragments: one ldmatrix.x4 per ni-pair per tile
#pragma unroll
            for (int pair = 0; pair < 2; pair++) {
                const int n = wn * 32 + pair * 16 + b_row_off;
                const uint32_t off = (uint32_t)(n * LDSW + kbase + b_col_off) * 2;
                ldsm_x4(bh[2 * pair][0], bh[2 * pair][1],
                        bh[2 * pair + 1][0], bh[2 * pair + 1][1], sBh + off);
                ldsm_x4(bl[2 * pair][0], bl[2 * pair][1],
                        bl[2 * pair + 1][0], bl[2 * pair + 1][1], sBl + off);
            }
#pragma unroll
            for (int mi = 0; mi < 4; mi++)
#pragma unroll
                for (int ni = 0; ni < 4; ni++) {
                    mma_bf16(acc[mi][ni], ah[mi], bh[ni]);
                    mma_bf16(acc[mi][ni], ah[mi], bl[ni]);
                    mma_bf16(acc[mi][ni], al[mi], bh[ni]);
                }
        }
        __syncthreads();
    }
}

// Fused QKV: z=0 -> Q (scaled, bf16 split out), z=1 -> K (split out), z=2 -> V (fp32)
__global__ __launch_bounds__(256, 2)
void qkv_gemm_fused()
{
    extern __shared__ char sm_[];
    const int z = blockIdx.z;
    const int bm = blockIdx.y, bn = blockIdx.x;
    const size_t woff = (size_t)z * D_MODEL * D_MODEL;

    float acc[4][4][4];
    gemm_core(g_Xhi + (size_t)(bm * 128) * KDIM,
              g_Xlo + (size_t)(bm * 128) * KDIM,
              g_Wthi + woff + (size_t)(bn * 128) * KDIM,
              g_Wtlo + woff + (size_t)(bn * 128) * KDIM,
              sm_, acc);

    const int t = threadIdx.x;
    const int lane = t & 31, wid = t >> 5;
    const int wm = wid >> 2, wn = wid & 3;
    const int rsub = lane >> 2, csub = (lane & 3) * 2;
    const int rowB = bm * 128 + wm * 64;
    const int colB = bn * 128 + wn * 32;

    if (z == 2) {
        float* Cb = g_V + (size_t)rowB * D_MODEL + colB;
#pragma unroll
        for (int mi = 0; mi < 4; mi++)
#pragma unroll
            for (int ni = 0; ni < 4; ni++) {
                const int row = mi * 16 + rsub;
                const int col = ni * 8 + csub;
                *reinterpret_cast<float2*>(Cb + (size_t)row * D_MODEL + col) =
                    make_float2(acc[mi][ni][0], acc[mi][ni][1]);
                *reinterpret_cast<float2*>(Cb + (size_t)(row + 8) * D_MODEL + col) =
                    make_float2(acc[mi][ni][2], acc[mi][ni][3]);
            }
    } else {
        const float scale = (z == 0) ? 0.08838834764831845f : 1.0f;
        __nv_bfloat16* Hi = (z == 0) ? g_Qhi : g_Khi;
        __nv_bfloat16* Lo = (z == 0) ? g_Qlo : g_Klo;
#pragma unroll
        for (int mi = 0; mi < 4; mi++)
#pragma unroll
            for (int ni = 0; ni < 4; ni++) {
                const int row = rowB + mi * 16 + rsub;
                const int col = colB + ni * 8 + csub;
#pragma unroll
                for (int half = 0; half < 2; half++) {
                    const int r = row + half * 8;
                    float v0 = acc[mi][ni][2 * half + 0] * scale;
                    float v1 = acc[mi][ni][2 * half + 1] * scale;
                    float h0 = __bfloat162float(__float2bfloat16(v0));
                    float h1 = __bfloat162float(__float2bfloat16(v1));
                    *reinterpret_cast<uint32_t*>(Hi + (size_t)r * D_MODEL + col) =
                        pack_bf16x2(h0, h1);
                    *reinterpret_cast<uint32_t*>(Lo + (size_t)r * D_MODEL + col) =
                        pack_bf16x2(v0 - h0, v1 - h1);
                }
            }
    }
}

// Output projection: fp32 epilogue straight to harness output
__global__ __launch_bounds__(256, 2)
void out_gemm(float* __restrict__ out)
{
    extern __shared__ char sm_[];
    const int bm = blockIdx.y, bn = blockIdx.x;
    const size_t woff = (size_t)3 * D_MODEL * D_MODEL;

    float acc[4][4][4];
    gemm_core(g_Ohi + (size_t)(bm * 128) * KDIM,
              g_Olo + (size_t)(bm * 128) * KDIM,
              g_Wthi + woff + (size_t)(bn * 128) * KDIM,
              g_Wtlo + woff + (size_t)(bn * 128) * KDIM,
              sm_, acc);

    const int t = threadIdx.x;
    const int lane = t & 31, wid = t >> 5;
    const int wm = wid >> 2, wn = wid & 3;
    const int rsub = lane >> 2, csub = (lane & 3) * 2;

    float* Cb = out + (size_t)(bm * 128 + wm * 64) * D_MODEL + bn * 128 + wn * 32;
#pragma unroll
    for (int mi = 0; mi < 4; mi++)
#pragma unroll
        for (int ni = 0; ni < 4; ni++) {
            const int row = mi * 16 + rsub;
            const int col = ni * 8 + csub;
            *reinterpret_cast<float2*>(Cb + (size_t)row * D_MODEL + col) =
                make_float2(acc[mi][ni][0], acc[mi][ni][1]);
            *reinterpret_cast<float2*>(Cb + (size_t)(row + 8) * D_MODEL + col) =
                make_float2(acc[mi][ni][2], acc[mi][ni][3]);
        }
}

// ---------------------------------------------------------------------------
// FA2-style attention on mma.sync (bf16 split precision).
// CTA = 128 queries x 1 head, 256 threads, 8 warps x 16 query rows.
// KV tiles of 64 keys, DOUBLE-BUFFERED via cp.async. Online softmax in fp32;
// P kept in registers. Epilogue writes O directly as bf16 hi/lo splits.
// ---------------------------------------------------------------------------
#define AQ 128
#define AK 64
#define QSTR 136   // bf16 elems per Q/K smem row (272 B) -> conflict-free
#define VSTR 72    // bf16 elems per Vt smem row (144 B) -> conflict-free

#define SM_QHI 0
#define SM_QLO (SM_QHI + AQ * QSTR * 2)          // 34816
#define SM_KV  (SM_QLO + AQ * QSTR * 2)          // 69632: start of KV stages
#define KV_KHI 0
#define KV_KLO (KV_KHI + AK * QSTR * 2)          // 17408
#define KV_VHI (KV_KLO + AK * QSTR * 2)          // 34816
#define KV_VLO (KV_VHI + HEAD_DIM * VSTR * 2)    // 53248
#define KV_STAGE (KV_VLO + HEAD_DIM * VSTR * 2)  // 71680
#define ATT_SMEM (SM_KV + 2 * KV_STAGE)          // 212992

__global__ __launch_bounds__(256, 1)
void mha_fa_mma()
{
    extern __shared__ char sm_[];
    const uint32_t sbase = smem_to_u32(sm_);
    const int t = threadIdx.x;
    const int lane = t & 31, wid = t >> 5;
    const int ib = gridDim.x - 1 - blockIdx.x;   // reversed: long CTAs first
    const int h = blockIdx.y;
    const int q0 = ib * AQ;
    const int rsub = lane >> 2, csub = (lane & 3) * 2;
    const int kk = csub;

    const __nv_bfloat16* sQh = (const __nv_bfloat16*)(sm_ + SM_QHI);
    const __nv_bfloat16* sQl = (const __nv_bfloat16*)(sm_ + SM_QLO);

    // ---- load Q tile (once), group 0 ----
    {
        const size_t gq = (size_t)q0 * D_MODEL + (size_t)h * HEAD_DIM;
#pragma unroll
        for (int i = 0; i < 8; i++) {
            const int idx = t + i * 256;
            const int row = idx >> 4, c = idx & 15;
            cp_async16(sbase + SM_QHI + row * (QSTR * 2) + c * 16,
                       g_Qhi + gq + (size_t)row * D_MODEL + c * 8);
            cp_async16(sbase + SM_QLO + row * (QSTR * 2) + c * 16,
                       g_Qlo + gq + (size_t)row * D_MODEL + c * 8);
        }
        CP_COMMIT();
    }

    const int nTiles = 2 * ib + 2;

    // ---- helper lambda: issue K/V loads for tile jb into given stage ----
    auto load_kv = [&](int jb, int stage) {
        const uint32_t kvb = sbase + SM_KV + stage * KV_STAGE;
        const int k0 = jb * AK;
        const size_t gk = (size_t)k0 * D_MODEL + (size_t)h * HEAD_DIM;
#pragma unroll
        for (int i = 0; i < 4; i++) {
            const int idx = t + i * 256;
            const int row = idx >> 4, c = idx & 15;
            cp_async16(kvb + KV_KHI + row * (QSTR * 2) + c * 16,
                       g_Khi + gk + (size_t)row * D_MODEL + c * 8);
            cp_async16(kvb + KV_KLO + row * (QSTR * 2) + c * 16,
                       g_Klo + gk + (size_t)row * D_MODEL + c * 8);
        }
        const size_t gv = (size_t)h * HEAD_DIM * S_LEN + k0;
#pragma unroll
        for (int i = 0; i < 4; i++) {
            const int idx = t + i * 256;
            const int row = idx >> 3, c = idx & 7;
            cp_async16(kvb + KV_VHI + row * (VSTR * 2) + c * 16,
                       g_Vthi + gv + (size_t)row * S_LEN + c * 8);
            cp_async16(kvb + KV_VLO + row * (VSTR * 2) + c * 16,
                       g_Vtlo + gv + (size_t)row * S_LEN + c * 8);
        }
        CP_COMMIT();
    };

    // preload tile 0 into stage 0 (group 1)
    load_kv(0, 0);

    float accO[16][4];
#pragma unroll
    for (int j = 0; j < 16; j++)
#pragma unroll
        for (int e = 0; e < 4; e++) accO[j][e] = 0.0f;
    float m0 = -1e30f, m1 = -1e30f, l0 = 0.0f, l1 = 0.0f;

    for (int jb = 0; jb < nTiles; jb++) {
        const int buf = jb & 1;
        // prefetch next tile into alternate stage, then wait for current tile
        if (jb + 1 < nTiles) {
            load_kv(jb + 1, buf ^ 1);
            CP_WAIT1();           // current tile (and Q) complete; next in flight
        } else {
            CP_WAIT0();
        }
        __syncthreads();

        const char* kvb = sm_ + SM_KV + buf * KV_STAGE;
        const __nv_bfloat16* sKh = (const __nv_bfloat16*)(kvb + KV_KHI);
        const __nv_bfloat16* sKl = (const __nv_bfloat16*)(kvb + KV_KLO);
        const __nv_bfloat16* sVh = (const __nv_bfloat16*)(kvb + KV_VHI);
        const __nv_bfloat16* sVl = (const __nv_bfloat16*)(kvb + KV_VLO);
        const int k0 = jb * AK;

        // ---- S = Q K^T (bf16x3) ----
        float accS[8][4];
#pragma unroll
        for (int j = 0; j < 8; j++)
#pragma unroll
            for (int e = 0; e < 4; e++) accS[j][e] = 0.0f;

#pragma unroll
        for (int ks = 0; ks < 8; ks++) {
            const int kc = ks * 16 + kk;
            uint32_t ah[4], al[4];
            {
                const int r0 = wid * 16 + rsub;
                const uint32_t* p0h = (const uint32_t*)(sQh + r0 * QSTR + kc);
                const uint32_t* p1h = (const uint32_t*)(sQh + (r0 + 8) * QSTR + kc);
                ah[0] = p0h[0]; ah[1] = p1h[0]; ah[2] = p0h[4]; ah[3] = p1h[4];
                const uint32_t* p0l = (const uint32_t*)(sQl + r0 * QSTR + kc);
                const uint32_t* p1l = (const uint32_t*)(sQl + (r0 + 8) * QSTR + kc);
                al[0] = p0l[0]; al[1] = p1l[0]; al[2] = p0l[4]; al[3] = p1l[4];
            }
#pragma unroll
            for (int j = 0; j < 8; j++) {
                const int rn = j * 8 + rsub;
                uint32_t bh[2], bl[2];
                const uint32_t* pbh = (const uint32_t*)(sKh + rn * QSTR + kc);
                bh[0] = pbh[0]; bh[1] = pbh[4];
                const uint32_t* pbl = (const uint32_t*)(sKl + rn * QSTR + kc);
                bl[0] = pbl[0]; bl[1] = pbl[4];
                mma_bf16(accS[j], ah, bh);
                mma_bf16(accS[j], ah, bl);
                mma_bf16(accS[j], al, bh);
            }
        }

        // ---- causal mask (only the two diagonal tiles) ----
        if (jb >= 2 * ib) {
            const int row0 = q0 + wid * 16 + rsub;
            const int row1 = row0 + 8;
#pragma unroll
            for (int j = 0; j < 8; j++) {
                const int c0 = k0 + j * 8 + csub;
                if (c0 > row0)     accS[j][0] = -1e30f;
                if (c0 + 1 > row0) accS[j][1] = -1e30f;
                if (c0 > row1)     accS[j][2] = -1e30f;
                if (c0 + 1 > row1) accS[j][3] = -1e30f;
            }
        }

        // ---- online softmax ----
        float mx0 = -1e30f, mx1 = -1e30f;
#pragma unroll
        for (int j = 0; j < 8; j++) {
            mx0 = fmaxf(mx0, fmaxf(accS[j][0], accS[j][1]));
            mx1 = fmaxf(mx1, fmaxf(accS[j][2], accS[j][3]));
        }
        mx0 = fmaxf(mx0, __shfl_xor_sync(0xffffffffu, mx0, 1));
        mx0 = fmaxf(mx0, __shfl_xor_sync(0xffffffffu, mx0, 2));
        mx1 = fmaxf(mx1, __shfl_xor_sync(0xffffffffu, mx1, 1));
        mx1 = fmaxf(mx1, __shfl_xor_sync(0xffffffffu, mx1, 2));

        const float mn0 = fmaxf(m0, mx0);
        const float mn1 = fmaxf(m1, mx1);
        const float al0 = __expf(m0 - mn0);
        const float al1 = __expf(m1 - mn1);
        m0 = mn0; m1 = mn1;

        float s0 = 0.0f, s1 = 0.0f;
#pragma unroll
        for (int j = 0; j < 8; j++) {
            accS[j][0] = __expf(accS[j][0] - m0);
            accS[j][1] = __expf(accS[j][1] - m0);
            accS[j][2] = __expf(accS[j][2] - m1);
            accS[j][3] = __expf(accS[j][3] - m1);
            s0 += accS[j][0] + accS[j][1];
            s1 += accS[j][2] + accS[j][3];
        }
        s0 += __shfl_xor_sync(0xffffffffu, s0, 1);
        s0 += __shfl_xor_sync(0xffffffffu, s0, 2);
        s1 += __shfl_xor_sync(0xffffffffu, s1, 1);
        s1 += __shfl_xor_sync(0xffffffffu, s1, 2);
        l0 = l0 * al0 + s0;
        l1 = l1 * al1 + s1;

#pragma unroll
        for (int j = 0; j < 16; j++) {
            accO[j][0] *= al0; accO[j][1] *= al0;
            accO[j][2] *= al1; accO[j][3] *= al1;
        }

        // ---- O += P V (bf16x3; P fragments straight from accS) ----
#pragma unroll
        for (int ks = 0; ks < 4; ks++) {
            uint32_t ph[4], pl[4];
            {
                const float* f0 = accS[2 * ks];
                const float* f1 = accS[2 * ks + 1];
                float h00 = __bfloat162float(__float2bfloat16(f0[0]));
                float h01 = __bfloat162float(__float2bfloat16(f0[1]));
                float h02 = __bfloat162float(__float2bfloat16(f0[2]));
                float h03 = __bfloat162float(__float2bfloat16(f0[3]));
                float h10 = __bfloat162float(__float2bfloat16(f1[0]));
                float h11 = __bfloat162float(__float2bfloat16(f1[1]));
                float h12 = __bfloat162float(__float2bfloat16(f1[2]));
                float h13 = __bfloat162float(__float2bfloat16(f1[3]));
                ph[0] = pack_bf16x2(h00, h01);
                ph[1] = pack_bf16x2(h02, h03);
                ph[2] = pack_bf16x2(h10, h11);
                ph[3] = pack_bf16x2(h12, h13);
                pl[0] = pack_bf16x2(f0[0] - h00, f0[1] - h01);
                pl[1] = pack_bf16x2(f0[2] - h02, f0[3] - h03);
                pl[2] = pack_bf16x2(f1[0] - h10, f1[1] - h11);
                pl[3] = pack_bf16x2(f1[2] - h12, f1[3] - h13);
            }
            const int kc = ks * 16 + kk;
#pragma unroll
            for (int j = 0; j < 16; j++) {
                const int rn = j * 8 + rsub;
                uint32_t bvh[2], bvl[2];
                const uint32_t* pvh = (const uint32_t*)(sVh + rn * VSTR + kc);
                bvh[0] = pvh[0]; bvh[1] = pvh[4];
                const uint32_t* pvl = (const uint32_t*)(sVl + rn * VSTR + kc);
                bvl[0] = pvl[0]; bvl[1] = pvl[4];
                mma_bf16(accO[j], ph, bvh);
                mma_bf16(accO[j], ph, bvl);
                mma_bf16(accO[j], pl, bvh);
            }
        }
        __syncthreads();   // all warps done reading this stage before it is re-filled
    }

    // ---- normalize + write O directly as bf16 hi/lo splits ----
    const float inv0 = 1.0f / l0;
    const float inv1 = 1.0f / l1;
    const size_t obase = (size_t)(q0 + wid * 16 + rsub) * D_MODEL + (size_t)h * HEAD_DIM;
#pragma unroll
    for (int j = 0; j < 16; j++) {
        const int col = j * 8 + csub;
#pragma unroll
        for (int half = 0; half < 2; half++) {
            const size_t off = obase + (size_t)(half * 8) * D_MODEL + col;
            float v0 = accO[j][2 * half + 0] * (half ? inv1 : inv0);
            float v1 = accO[j][2 * half + 1] * (half ? inv1 : inv0);
            float h0 = __bfloat162float(__float2bfloat16(v0));
            float h1 = __bfloat162float(__float2bfloat16(v1));
            *reinterpret_cast<uint32_t*>(g_Ohi + off) = pack_bf16x2(h0, h1);
            *reinterpret_cast<uint32_t*>(g_Olo + off) = pack_bf16x2(v0 - h0, v1 - h1);
        }
    }
}

// ---------------------------------------------------------------------------
// Launch
// ---------------------------------------------------------------------------
extern "C" void kernel_launch(void* const* d_in, const int* in_sizes, int n_in,
                              void* d_out, int out_size)
{
    const float* X  = (const float*)d_in[0];
    const float* Wq = (const float*)d_in[1];
    const float* Wk = (const float*)d_in[2];
    const float* Wv = (const float*)d_in[3];
    const float* Wo = (const float*)d_in[4];
    float* out = (float*)d_out;

    cudaFuncSetAttribute(qkv_gemm_fused, cudaFuncAttributeMaxDynamicSharedMemorySize, GEMM_SMEM);
    cudaFuncSetAttribute(out_gemm, cudaFuncAttributeMaxDynamicSharedMemorySize, GEMM_SMEM);
    cudaFuncSetAttribute(mha_fa_mma, cudaFuncAttributeMaxDynamicSharedMemorySize, ATT_SMEM);

    const int nElem = S_LEN * D_MODEL;

    // 1) split X; transpose+split weights
    split_x_kernel<<<nElem / 256, 256>>>(X);
    dim3 wb(32, 8), wg(D_MODEL / 32, D_MODEL / 32, 4);
    wsplit_t_kernel<<<wg, wb>>>(Wq, Wk, Wv, Wo);

    // 2) fused QKV projections (Q/K write bf16 splits directly; V fp32)
    dim3 gq(D_MODEL / 128, S_LEN / 128, 3);
    qkv_gemm_fused<<<gq, 256, GEMM_SMEM>>>();

    // 3) V transpose+split for attention
    dim3 vb(32, 8), vg(D_MODEL / 32, S_LEN / 32);
    vt_split_kernel<<<vg, vb>>>();

    // 4) causal flash attention on tensor cores (double-buffered K/V)
    dim3 gatt(S_LEN / AQ, N_HEADS);
    mha_fa_mma<<<gatt, 256, ATT_SMEM>>>();

    // 5) output projection straight to harness buffer
    dim3 go(D_MODEL / 128, S_LEN / 128);
    out_gemm<<<go, 256, GEMM_SMEM>>>(out);
}

// round 14
// speedup vs baseline: 3.1788x; 1.0165x over previous
#include <cuda_runtime.h>
#include <cuda_bf16.h>
#include <math.h>
#include <stdint.h>

// Problem constants (fixed by the reference: B=1, S=4096, D=2048, H=16)
#define S_LEN    4096
#define D_MODEL  2048
#define KDIM     2048
#define N_HEADS  16
#define HEAD_DIM 128

// ---------------------------------------------------------------------------
// Scratch (__device__ globals; allocation-free rule)
// ---------------------------------------------------------------------------
__device__ float g_V[(size_t)S_LEN * D_MODEL];

__device__ __nv_bfloat16 g_Xhi[(size_t)S_LEN * D_MODEL];
__device__ __nv_bfloat16 g_Xlo[(size_t)S_LEN * D_MODEL];
__device__ __nv_bfloat16 g_Ohi[(size_t)S_LEN * D_MODEL];
__device__ __nv_bfloat16 g_Olo[(size_t)S_LEN * D_MODEL];
__device__ __nv_bfloat16 g_Wthi[(size_t)4 * D_MODEL * D_MODEL];
__device__ __nv_bfloat16 g_Wtlo[(size_t)4 * D_MODEL * D_MODEL];

// attention operands (bf16 hi/lo). Q pre-scaled by 1/sqrt(hd).
__device__ __nv_bfloat16 g_Qhi[(size_t)S_LEN * D_MODEL];
__device__ __nv_bfloat16 g_Qlo[(size_t)S_LEN * D_MODEL];
__device__ __nv_bfloat16 g_Khi[(size_t)S_LEN * D_MODEL];
__device__ __nv_bfloat16 g_Klo[(size_t)S_LEN * D_MODEL];
// V transposed per head: Vt[c][s] where c = h*128 + d  -> [D_MODEL][S_LEN]
__device__ __nv_bfloat16 g_Vthi[(size_t)D_MODEL * S_LEN];
__device__ __nv_bfloat16 g_Vtlo[(size_t)D_MODEL * S_LEN];

// ---------------------------------------------------------------------------
// Portable helpers (sm_80+): cp.async + mma.sync bf16 + ldmatrix
// ---------------------------------------------------------------------------
__device__ __forceinline__ uint32_t smem_to_u32(const void* p) {
    uint32_t a;
    asm("{ .reg .u64 t; cvta.to.shared.u64 t, %1; cvt.u32.u64 %0, t; }" : "=r"(a) : "l"(p));
    return a;
}
__device__ __forceinline__ void cp_async16(uint32_t dst, const void* src) {
    asm volatile("cp.async.cg.shared.global [%0], [%1], 16;" :: "r"(dst), "l"(src));
}
#define CP_COMMIT() asm volatile("cp.async.commit_group;" ::: "memory")
#define CP_WAIT1()  asm volatile("cp.async.wait_group 1;" ::: "memory")
#define CP_WAIT0()  asm volatile("cp.async.wait_group 0;" ::: "memory")

__device__ __forceinline__ void mma_bf16(float* c, const uint32_t* a, const uint32_t* b) {
    asm volatile(
        "mma.sync.aligned.m16n8k16.row.col.f32.bf16.bf16.f32 "
        "{%0,%1,%2,%3}, {%4,%5,%6,%7}, {%8,%9}, {%0,%1,%2,%3};"
        : "+f"(c[0]), "+f"(c[1]), "+f"(c[2]), "+f"(c[3])
        : "r"(a[0]), "r"(a[1]), "r"(a[2]), "r"(a[3]), "r"(b[0]), "r"(b[1]));
}
__device__ __forceinline__ void ldsm_x4(uint32_t& r0, uint32_t& r1, uint32_t& r2, uint32_t& r3,
                                        uint32_t addr) {
    asm volatile("ldmatrix.sync.aligned.m8n8.x4.shared.b16 {%0,%1,%2,%3}, [%4];"
                 : "=r"(r0), "=r"(r1), "=r"(r2), "=r"(r3) : "r"(addr));
}
__device__ __forceinline__ uint32_t pack_bf16x2(float lo, float hi) {
    __nv_bfloat162 v = __float22bfloat162_rn(make_float2(lo, hi));
    return *reinterpret_cast<uint32_t*>(&v);
}

// ---------------------------------------------------------------------------
// Prep kernels
// ---------------------------------------------------------------------------
__global__ void split_x_kernel(const float* __restrict__ X) {
    size_t i = (size_t)blockIdx.x * blockDim.x + threadIdx.x;
    float v = X[i];
    __nv_bfloat16 h = __float2bfloat16(v);
    g_Xhi[i] = h;
    g_Xlo[i] = __float2bfloat16(v - __bfloat162float(h));
}
__global__ void wsplit_t_kernel(const float* __restrict__ Wq, const float* __restrict__ Wk,
                                const float* __restrict__ Wv, const float* __restrict__ Wo) {
    __shared__ float tile[32][33];
    const int w = blockIdx.z;
    const float* W = (w == 0) ? Wq : (w == 1) ? Wk : (w == 2) ? Wv : Wo;
    const size_t off = (size_t)w * D_MODEL * D_MODEL;
    const int n0 = blockIdx.x * 32, k0 = blockIdx.y * 32;
    const int tx = threadIdx.x, ty = threadIdx.y;  // (32, 8)
#pragma unroll
    for (int i = 0; i < 32; i += 8)
        tile[ty + i][tx] = W[(size_t)(k0 + ty + i) * D_MODEL + n0 + tx];
    __syncthreads();
#pragma unroll
    for (int i = 0; i < 32; i += 8) {
        int n = n0 + ty + i, k = k0 + tx;
        float v = tile[tx][ty + i];
        __nv_bfloat16 h = __float2bfloat16(v);
        g_Wthi[off + (size_t)n * KDIM + k] = h;
        g_Wtlo[off + (size_t)n * KDIM + k] = __float2bfloat16(v - __bfloat162float(h));
    }
}
// V [S][D] fp32 -> Vt hi/lo [D][S] bf16 (coalesced 32x32 transpose)
__global__ void vt_split_kernel() {
    __shared__ float tile[32][33];
    const int s0 = blockIdx.y * 32, c0 = blockIdx.x * 32;
    const int tx = threadIdx.x, ty = threadIdx.y;  // (32, 8)
#pragma unroll
    for (int i = 0; i < 32; i += 8)
        tile[ty + i][tx] = g_V[(size_t)(s0 + ty + i) * D_MODEL + c0 + tx];
    __syncthreads();
#pragma unroll
    for (int i = 0; i < 32; i += 8) {
        int c = c0 + ty + i, s = s0 + tx;
        float v = tile[tx][ty + i];
        __nv_bfloat16 h = __float2bfloat16(v);
        g_Vthi[(size_t)c * S_LEN + s] = h;
        g_Vtlo[(size_t)c * S_LEN + s] = __float2bfloat16(v - __bfloat162float(h));
    }
}

// ---------------------------------------------------------------------------
// bf16x3 tensor-core GEMM core (compute accumulators for one 128x128 tile).
// Block 128x128xK32, 256 threads (8 warps 2x4), warp tile 64x32.
// Fragment loads via ldmatrix.x4 (12 LDSM/ks vs 48 LDS.32/ks).
// ---------------------------------------------------------------------------
#define LDSW 40
#define TILE_B (128 * LDSW * 2)
#define STAGE_B (4 * TILE_B)
#define GEMM_SMEM (2 * STAGE_B)
#define NSTAGE (KDIM / 32)

__device__ __forceinline__ void gemm_core(const __nv_bfloat16* __restrict__ Ah,
                                          const __nv_bfloat16* __restrict__ Al,
                                          const __nv_bfloat16* __restrict__ Bh,
                                          const __nv_bfloat16* __restrict__ Bl,
                                          char* sm_, float acc[4][4][4])
{
    const int t = threadIdx.x;
    const int lane = t & 31, wid = t >> 5;
    const int wm = wid >> 2, wn = wid & 3;
    const uint32_t sbase = smem_to_u32(sm_);

#pragma unroll
    for (int mi = 0; mi < 4; mi++)
#pragma unroll
        for (int ni = 0; ni < 4; ni++)
#pragma unroll
            for (int e = 0; e < 4; e++) acc[mi][ni][e] = 0.0f;

    const int ldr = t >> 2;
    const int kc  = t & 3;
    const __nv_bfloat16* srcs[4] = { Ah, Al, Bh, Bl };

    // ldmatrix lane-address components (per warp):
    const int lr = lane & 7;       // row within 8x8 matrix
    const int lg = lane >> 3;      // matrix group 0..3
    const int a_row_off = (lg & 1) * 8 + lr;
    const int a_col_off = (lg >> 1) * 8;
    const int b_row_off = ((lg >> 1) & 1) * 8 + lr;
    const int b_col_off = (lg & 1) * 8;

    {
        const uint32_t dbase = sbase;
#pragma unroll
        for (int j = 0; j < 8; j++) {
            const int tile = j >> 1;
            const int row = (j & 1) * 64 + ldr;
            cp_async16(dbase + tile * TILE_B + row * 80 + kc * 16,
                       srcs[tile] + (size_t)row * KDIM + kc * 8);
        }
        CP_COMMIT();
    }

    for (int kt = 0; kt < NSTAGE; kt++) {
        if (kt + 1 < NSTAGE) {
            const int k0 = (kt + 1) * 32;
            const uint32_t dbase = sbase + ((kt + 1) & 1) * STAGE_B;
#pragma unroll
            for (int j = 0; j < 8; j++) {
                const int tile = j >> 1;
                const int row = (j & 1) * 64 + ldr;
                cp_async16(dbase + tile * TILE_B + row * 80 + kc * 16,
                           srcs[tile] + (size_t)row * KDIM + k0 + kc * 8);
            }
            CP_COMMIT();
            CP_WAIT1();
        } else {
            CP_WAIT0();
        }
        __syncthreads();

        const uint32_t stb = sbase + (kt & 1) * STAGE_B;
        const uint32_t sAh = stb;
        const uint32_t sAl = stb + TILE_B;
        const uint32_t sBh = stb + 2 * TILE_B;
        const uint32_t sBl = stb + 3 * TILE_B;

#pragma unroll
        for (int ks = 0; ks < 2; ks++) {
            const int kbase = ks * 16;

            uint32_t ah[4][4], al[4][4], bh[4][2], bl[4][2];
#pragma unroll
            for (int mi = 0; mi < 4; mi++) {
                const int r = wm * 64 + mi * 16 + a_row_off;
                const uint32_t off = (uint32_t)(r * LDSW + kbase + a_col_off) * 2;
                ldsm_x4(ah[mi][0], ah[mi][1], ah[mi][2], ah[mi][3], sAh + off);
                ldsm_x4(al[mi][0], al[mi][1], al[mi][2], al[mi][3], sAl + off);
            }
#pragma unroll
            for (int pair = 0; pair < 2; pair++) {
                const int n = wn * 32 + pair * 16 + b_row_off;
                const uint32_t off = (uint32_t)(n * LDSW + kbase + b_col_off) * 2;
                ldsm_x4(bh[2 * pair][0], bh[2 * pair][1],
                        bh[2 * pair + 1][0], bh[2 * pair + 1][1], sBh + off);
                ldsm_x4(bl[2 * pair][0], bl[2 * pair][1],
                        bl[2 * pair + 1][0], bl[2 * pair + 1][1], sBl + off);
            }
#pragma unroll
            for (int mi = 0; mi < 4; mi++)
#pragma unroll
                for (int ni = 0; ni < 4; ni++) {
                    mma_bf16(acc[mi][ni], ah[mi], bh[ni]);
                    mma_bf16(acc[mi][ni], ah[mi], bl[ni]);
                    mma_bf16(acc[mi][ni], al[mi], bh[ni]);
                }
        }
        __syncthreads();
    }
}

// Fused QKV: z=0 -> Q (scaled, bf16 split out), z=1 -> K (split out), z=2 -> V (fp32)
__global__ __launch_bounds__(256, 2)
void qkv_gemm_fused()
{
    extern __shared__ char sm_[];
    const int z = blockIdx.z;
    const int bm = blockIdx.y, bn = blockIdx.x;
    const size_t woff = (size_t)z * D_MODEL * D_MODEL;

    float acc[4][4][4];
    gemm_core(g_Xhi + (size_t)(bm * 128) * KDIM,
              g_Xlo + (size_t)(bm * 128) * KDIM,
              g_Wthi + woff + (size_t)(bn * 128) * KDIM,
              g_Wtlo + woff + (size_t)(bn * 128) * KDIM,
              sm_, acc);

    const int t = threadIdx.x;
    const int lane = t & 31, wid = t >> 5;
    const int wm = wid >> 2, wn = wid & 3;
    const int rsub = lane >> 2, csub = (lane & 3) * 2;
    const int rowB = bm * 128 + wm * 64;
    const int colB = bn * 128 + wn * 32;

    if (z == 2) {
        float* Cb = g_V + (size_t)rowB * D_MODEL + colB;
#pragma unroll
        for (int mi = 0; mi < 4; mi++)
#pragma unroll
            for (int ni = 0; ni < 4; ni++) {
                const int row = mi * 16 + rsub;
                const int col = ni * 8 + csub;
                *reinterpret_cast<float2*>(Cb + (size_t)row * D_MODEL + col) =
                    make_float2(acc[mi][ni][0], acc[mi][ni][1]);
                *reinterpret_cast<float2*>(Cb + (size_t)(row + 8) * D_MODEL + col) =
                    make_float2(acc[mi][ni][2], acc[mi][ni][3]);
            }
    } else {
        const float scale = (z == 0) ? 0.08838834764831845f : 1.0f;
        __nv_bfloat16* Hi = (z == 0) ? g_Qhi : g_Khi;
        __nv_bfloat16* Lo = (z == 0) ? g_Qlo : g_Klo;
#pragma unroll
        for (int mi = 0; mi < 4; mi++)
#pragma unroll
            for (int ni = 0; ni < 4; ni++) {
                const int row = rowB + mi * 16 + rsub;
                const int col = colB + ni * 8 + csub;
#pragma unroll
                for (int half = 0; half < 2; half++) {
                    const int r = row + half * 8;
                    float v0 = acc[mi][ni][2 * half + 0] * scale;
                    float v1 = acc[mi][ni][2 * half + 1] * scale;
                    float h0 = __bfloat162float(__float2bfloat16(v0));
                    float h1 = __bfloat162float(__float2bfloat16(v1));
                    *reinterpret_cast<uint32_t*>(Hi + (size_t)r * D_MODEL + col) =
                        pack_bf16x2(h0, h1);
                    *reinterpret_cast<uint32_t*>(Lo + (size_t)r * D_MODEL + col) =
                        pack_bf16x2(v0 - h0, v1 - h1);
                }
            }
    }
}

// Output projection: fp32 epilogue straight to harness output
__global__ __launch_bounds__(256, 2)
void out_gemm(float* __restrict__ out)
{
    extern __shared__ char sm_[];
    const int bm = blockIdx.y, bn = blockIdx.x;
    const size_t woff = (size_t)3 * D_MODEL * D_MODEL;

    float acc[4][4][4];
    gemm_core(g_Ohi + (size_t)(bm * 128) * KDIM,
              g_Olo + (size_t)(bm * 128) * KDIM,
              g_Wthi + woff + (size_t)(bn * 128) * KDIM,
              g_Wtlo + woff + (size_t)(bn * 128) * KDIM,
              sm_, acc);

    const int t = threadIdx.x;
    const int lane = t & 31, wid = t >> 5;
    const int wm = wid >> 2, wn = wid & 3;
    const int rsub = lane >> 2, csub = (lane & 3) * 2;

    float* Cb = out + (size_t)(bm * 128 + wm * 64) * D_MODEL + bn * 128 + wn * 32;
#pragma unroll
    for (int mi = 0; mi < 4; mi++)
#pragma unroll
        for (int ni = 0; ni < 4; ni++) {
            const int row = mi * 16 + rsub;
            const int col = ni * 8 + csub;
            *reinterpret_cast<float2*>(Cb + (size_t)row * D_MODEL + col) =
                make_float2(acc[mi][ni][0], acc[mi][ni][1]);
            *reinterpret_cast<float2*>(Cb + (size_t)(row + 8) * D_MODEL + col) =
                make_float2(acc[mi][ni][2], acc[mi][ni][3]);
        }
}

// ---------------------------------------------------------------------------
// FA2-style attention on mma.sync (bf16 split precision).
// CTA = 128 queries x 1 head, 256 threads, 8 warps x 16 query rows.
// KV tiles of 64 keys, DOUBLE-BUFFERED via cp.async. Fragment loads via
// ldmatrix.x4. Online softmax in fp32; P kept in registers.
// Epilogue writes O directly as bf16 hi/lo splits.
// ---------------------------------------------------------------------------
#define AQ 128
#define AK 64
#define QSTR 136   // bf16 elems per Q/K smem row (272 B) -> conflict-free
#define VSTR 72    // bf16 elems per Vt smem row (144 B) -> conflict-free

#define SM_QHI 0
#define SM_QLO (SM_QHI + AQ * QSTR * 2)          // 34816
#define SM_KV  (SM_QLO + AQ * QSTR * 2)          // 69632: start of KV stages
#define KV_KHI 0
#define KV_KLO (KV_KHI + AK * QSTR * 2)          // 17408
#define KV_VHI (KV_KLO + AK * QSTR * 2)          // 34816
#define KV_VLO (KV_VHI + HEAD_DIM * VSTR * 2)    // 53248
#define KV_STAGE (KV_VLO + HEAD_DIM * VSTR * 2)  // 71680
#define ATT_SMEM (SM_KV + 2 * KV_STAGE)          // 212992

__global__ __launch_bounds__(256, 1)
void mha_fa_mma()
{
    extern __shared__ char sm_[];
    const uint32_t sbase = smem_to_u32(sm_);
    const int t = threadIdx.x;
    const int lane = t & 31, wid = t >> 5;
    const int ib = gridDim.x - 1 - blockIdx.x;   // reversed: long CTAs first
    const int h = blockIdx.y;
    const int q0 = ib * AQ;
    const int rsub = lane >> 2, csub = (lane & 3) * 2;

    // ldmatrix lane-address components
    const int lr = lane & 7;
    const int lg = lane >> 3;
    const int a_row_off = (lg & 1) * 8 + lr;     // A operand (Q)
    const int a_col_off = (lg >> 1) * 8;
    const int b_row_off = ((lg >> 1) & 1) * 8 + lr;  // B operand (K / Vt)
    const int b_col_off = (lg & 1) * 8;

    const uint32_t sQh = sbase + SM_QHI;
    const uint32_t sQl = sbase + SM_QLO;

    // ---- load Q tile (once), group 0 ----
    {
        const size_t gq = (size_t)q0 * D_MODEL + (size_t)h * HEAD_DIM;
#pragma unroll
        for (int i = 0; i < 8; i++) {
            const int idx = t + i * 256;
            const int row = idx >> 4, c = idx & 15;
            cp_async16(sQh + row * (QSTR * 2) + c * 16,
                       g_Qhi + gq + (size_t)row * D_MODEL + c * 8);
            cp_async16(sQl + row * (QSTR * 2) + c * 16,
                       g_Qlo + gq + (size_t)row * D_MODEL + c * 8);
        }
        CP_COMMIT();
    }

    const int nTiles = 2 * ib + 2;

    // ---- helper lambda: issue K/V loads for tile jb into given stage ----
    auto load_kv = [&](int jb, int stage) {
        const uint32_t kvb = sbase + SM_KV + stage * KV_STAGE;
        const int k0 = jb * AK;
        const size_t gk = (size_t)k0 * D_MODEL + (size_t)h * HEAD_DIM;
#pragma unroll
        for (int i = 0; i < 4; i++) {
            const int idx = t + i * 256;
            const int row = idx >> 4, c = idx & 15;
            cp_async16(kvb + KV_KHI + row * (QSTR * 2) + c * 16,
                       g_Khi + gk + (size_t)row * D_MODEL + c * 8);
            cp_async16(kvb + KV_KLO + row * (QSTR * 2) + c * 16,
                       g_Klo + gk + (size_t)row * D_MODEL + c * 8);
        }
        const size_t gv = (size_t)h * HEAD_DIM * S_LEN + k0;
#pragma unroll
        for (int i = 0; i < 4; i++) {
            const int idx = t + i * 256;
            const int row = idx >> 3, c = idx & 7;
            cp_async16(kvb + KV_VHI + row * (VSTR * 2) + c * 16,
                       g_Vthi + gv + (size_t)row * S_LEN + c * 8);
            cp_async16(kvb + KV_VLO + row * (VSTR * 2) + c * 16,
                       g_Vtlo + gv + (size_t)row * S_LEN + c * 8);
        }
        CP_COMMIT();
    };

    // preload tile 0 into stage 0 (group 1)
    load_kv(0, 0);

    float accO[16][4];
#pragma unroll
    for (int j = 0; j < 16; j++)
#pragma unroll
        for (int e = 0; e < 4; e++) accO[j][e] = 0.0f;
    float m0 = -1e30f, m1 = -1e30f, l0 = 0.0f, l1 = 0.0f;

    for (int jb = 0; jb < nTiles; jb++) {
        const int buf = jb & 1;
        if (jb + 1 < nTiles) {
            load_kv(jb + 1, buf ^ 1);
            CP_WAIT1();
        } else {
            CP_WAIT0();
        }
        __syncthreads();

        const uint32_t kvb = sbase + SM_KV + buf * KV_STAGE;
        const uint32_t sKh = kvb + KV_KHI;
        const uint32_t sKl = kvb + KV_KLO;
        const uint32_t sVh = kvb + KV_VHI;
        const uint32_t sVl = kvb + KV_VLO;
        const int k0 = jb * AK;

        // ---- S = Q K^T (bf16x3, ldmatrix fragments) ----
        float accS[8][4];
#pragma unroll
        for (int j = 0; j < 8; j++)
#pragma unroll
            for (int e = 0; e < 4; e++) accS[j][e] = 0.0f;

#pragma unroll
        for (int ks = 0; ks < 8; ks++) {
            const int kbase = ks * 16;
            uint32_t ah[4], al[4];
            {
                const int r = wid * 16 + a_row_off;
                const uint32_t off = (uint32_t)(r * QSTR + kbase + a_col_off) * 2;
                ldsm_x4(ah[0], ah[1], ah[2], ah[3], sQh + off);
                ldsm_x4(al[0], al[1], al[2], al[3], sQl + off);
            }
#pragma unroll
            for (int pair = 0; pair < 4; pair++) {
                const int n = pair * 16 + b_row_off;
                const uint32_t off = (uint32_t)(n * QSTR + kbase + b_col_off) * 2;
                uint32_t bh0[2], bh1[2], bl0[2], bl1[2];
                ldsm_x4(bh0[0], bh0[1], bh1[0], bh1[1], sKh + off);
                ldsm_x4(bl0[0], bl0[1], bl1[0], bl1[1], sKl + off);
                mma_bf16(accS[2 * pair], ah, bh0);
                mma_bf16(accS[2 * pair], ah, bl0);
                mma_bf16(accS[2 * pair], al, bh0);
                mma_bf16(accS[2 * pair + 1], ah, bh1);
                mma_bf16(accS[2 * pair + 1], ah, bl1);
                mma_bf16(accS[2 * pair + 1], al, bh1);
            }
        }

        // ---- causal mask (only the two diagonal tiles) ----
        if (jb >= 2 * ib) {
            const int row0 = q0 + wid * 16 + rsub;
            const int row1 = row0 + 8;
#pragma unroll
            for (int j = 0; j < 8; j++) {
                const int c0 = k0 + j * 8 + csub;
                if (c0 > row0)     accS[j][0] = -1e30f;
                if (c0 + 1 > row0) accS[j][1] = -1e30f;
                if (c0 > row1)     accS[j][2] = -1e30f;
                if (c0 + 1 > row1) accS[j][3] = -1e30f;
            }
        }

        // ---- online softmax ----
        float mx0 = -1e30f, mx1 = -1e30f;
#pragma unroll
        for (int j = 0; j < 8; j++) {
            mx0 = fmaxf(mx0, fmaxf(accS[j][0], accS[j][1]));
            mx1 = fmaxf(mx1, fmaxf(accS[j][2], accS[j][3]));
        }
        mx0 = fmaxf(mx0, __shfl_xor_sync(0xffffffffu, mx0, 1));
        mx0 = fmaxf(mx0, __shfl_xor_sync(0xffffffffu, mx0, 2));
        mx1 = fmaxf(mx1, __shfl_xor_sync(0xffffffffu, mx1, 1));
        mx1 = fmaxf(mx1, __shfl_xor_sync(0xffffffffu, mx1, 2));

        const float mn0 = fmaxf(m0, mx0);
        const float mn1 = fmaxf(m1, mx1);
        const float al0 = __expf(m0 - mn0);
        const float al1 = __expf(m1 - mn1);
        m0 = mn0; m1 = mn1;

        float s0 = 0.0f, s1 = 0.0f;
#pragma unroll
        for (int j = 0; j < 8; j++) {
            accS[j][0] = __expf(accS[j][0] - m0);
            accS[j][1] = __expf(accS[j][1] - m0);
            accS[j][2] = __expf(accS[j][2] - m1);
            accS[j][3] = __expf(accS[j][3] - m1);
            s0 += accS[j][0] + accS[j][1];
            s1 += accS[j][2] + accS[j][3];
        }
        s0 += __shfl_xor_sync(0xffffffffu, s0, 1);
        s0 += __shfl_xor_sync(0xffffffffu, s0, 2);
        s1 += __shfl_xor_sync(0xffffffffu, s1, 1);
        s1 += __shfl_xor_sync(0xffffffffu, s1, 2);
        l0 = l0 * al0 + s0;
        l1 = l1 * al1 + s1;

#pragma unroll
        for (int j = 0; j < 16; j++) {
            accO[j][0] *= al0; accO[j][1] *= al0;
            accO[j][2] *= al1; accO[j][3] *= al1;
        }

        // ---- O += P V (bf16x3; P fragments straight from accS) ----
#pragma unroll
        for (int ks = 0; ks < 4; ks++) {
            uint32_t ph[4], pl[4];
            {
                const float* f0 = accS[2 * ks];
                const float* f1 = accS[2 * ks + 1];
                float h00 = __bfloat162float(__float2bfloat16(f0[0]));
                float h01 = __bfloat162float(__float2bfloat16(f0[1]));
                float h02 = __bfloat162float(__float2bfloat16(f0[2]));
                float h03 = __bfloat162float(__float2bfloat16(f0[3]));
                float h10 = __bfloat162float(__float2bfloat16(f1[0]));
                float h11 = __bfloat162float(__float2bfloat16(f1[1]));
                float h12 = __bfloat162float(__float2bfloat16(f1[2]));
                float h13 = __bfloat162float(__float2bfloat16(f1[3]));
                ph[0] = pack_bf16x2(h00, h01);
                ph[1] = pack_bf16x2(h02, h03);
                ph[2] = pack_bf16x2(h10, h11);
                ph[3] = pack_bf16x2(h12, h13);
                pl[0] = pack_bf16x2(f0[0] - h00, f0[1] - h01);
                pl[1] = pack_bf16x2(f0[2] - h02, f0[3] - h03);
                pl[2] = pack_bf16x2(f1[0] - h10, f1[1] - h11);
                pl[3] = pack_bf16x2(f1[2] - h12, f1[3] - h13);
            }
            const int kbase = ks * 16;
#pragma unroll
            for (int pair = 0; pair < 8; pair++) {
                const int n = pair * 16 + b_row_off;
                const uint32_t off = (uint32_t)(n * VSTR + kbase + b_col_off) * 2;
                uint32_t vh0[2], vh1[2], vl0[2], vl1[2];
                ldsm_x4(vh0[0], vh0[1], vh1[0], vh1[1], sVh + off);
                ldsm_x4(vl0[0], vl0[1], vl1[0], vl1[1], sVl + off);
                mma_bf16(accO[2 * pair], ph, vh0);
                mma_bf16(accO[2 * pair], ph, vl0);
                mma_bf16(accO[2 * pair], pl, vh0);
                mma_bf16(accO[2 * pair + 1], ph, vh1);
                mma_bf16(accO[2 * pair + 1], ph, vl1);
                mma_bf16(accO[2 * pair + 1], pl, vh1);
            }
        }
        __syncthreads();   // all warps done reading this stage before it is re-filled
    }

    // ---- normalize + write O directly as bf16 hi/lo splits ----
    const float inv0 = 1.0f / l0;
    const float inv1 = 1.0f / l1;
    const size_t obase = (size_t)(q0 + wid * 16 + rsub) * D_MODEL + (size_t)h * HEAD_DIM;
#pragma unroll
    for (int j = 0; j < 16; j++) {
        const int col = j * 8 + csub;
#pragma unroll
        for (int half = 0; half < 2; half++) {
            const size_t off = obase + (size_t)(half * 8) * D_MODEL + col;
            float v0 = accO[j][2 * half + 0] * (half ? inv1 : inv0);
            float v1 = accO[j][2 * half + 1] * (half ? inv1 : inv0);
            float h0 = __bfloat162float(__float2bfloat16(v0));
            float h1 = __bfloat162float(__float2bfloat16(v1));
            *reinterpret_cast<uint32_t*>(g_Ohi + off) = pack_bf16x2(h0, h1);
            *reinterpret_cast<uint32_t*>(g_Olo + off) = pack_bf16x2(v0 - h0, v1 - h1);
        }
    }
}

// ---------------------------------------------------------------------------
// Launch
// ---------------------------------------------------------------------------
extern "C" void kernel_launch(void* const* d_in, const int* in_sizes, int n_in,
                              void* d_out, int out_size)
{
    const float* X  = (const float*)d_in[0];
    const float* Wq = (const float*)d_in[1];
    const float* Wk = (const float*)d_in[2];
    const float* Wv = (const float*)d_in[3];
    const float* Wo = (const float*)d_in[4];
    float* out = (float*)d_out;

    cudaFuncSetAttribute(qkv_gemm_fused, cudaFuncAttributeMaxDynamicSharedMemorySize, GEMM_SMEM);
    cudaFuncSetAttribute(out_gemm, cudaFuncAttributeMaxDynamicSharedMemorySize, GEMM_SMEM);
    cudaFuncSetAttribute(mha_fa_mma, cudaFuncAttributeMaxDynamicSharedMemorySize, ATT_SMEM);

    const int nElem = S_LEN * D_MODEL;

    // 1) split X; transpose+split weights
    split_x_kernel<<<nElem / 256, 256>>>(X);
    dim3 wb(32, 8), wg(D_MODEL / 32, D_MODEL / 32, 4);
    wsplit_t_kernel<<<wg, wb>>>(Wq, Wk, Wv, Wo);

    // 2) fused QKV projections (Q/K write bf16 splits directly; V fp32)
    dim3 gq(D_MODEL / 128, S_LEN / 128, 3);
    qkv_gemm_fused<<<gq, 256, GEMM_SMEM>>>();

    // 3) V transpose+split for attention
    dim3 vb(32, 8), vg(D_MODEL / 32, S_LEN / 32);
    vt_split_kernel<<<vg, vb>>>();

    // 4) causal flash attention on tensor cores (double-buffered K/V, ldmatrix)
    dim3 gatt(S_LEN / AQ, N_HEADS);
    mha_fa_mma<<<gatt, 256, ATT_SMEM>>>();

    // 5) output projection straight to harness buffer
    dim3 go(D_MODEL / 128, S_LEN / 128);
    out_gemm<<<go, 256, GEMM_SMEM>>>(out);
}